// round 1
// baseline (speedup 1.0000x reference)
#include <cuda_runtime.h>
#include <math.h>

// ---------------------------------------------------------------------------
// Problem constants (fixed by setup_inputs)
// ---------------------------------------------------------------------------
#define Bsz   8
#define Himg  128
#define Wimg  128
#define Cdim  192
#define HID   768
#define WS    8
#define SHIFT 4
#define NH    6
#define HD    32          // head dim
#define NTOK  (Bsz*Himg*Wimg)        // 131072 tokens
#define NWIN  (Bsz*(Himg/WS)*(Wimg/WS))   // 2048 windows
#define NPW   (WS*WS)                // 64 tokens / window

// ---------------------------------------------------------------------------
// Scratch (static device globals; no allocation at runtime)
// ---------------------------------------------------------------------------
__device__ float g_win[(size_t)NTOK * Cdim];   // LN1+shift+window output / reused for proj out
__device__ float g_qkv[(size_t)NTOK * 3 * Cdim];
__device__ float g_att[(size_t)NTOK * Cdim];   // attention output (window layout)
__device__ float g_x1 [(size_t)NTOK * Cdim];   // residual after attention branch
__device__ float g_ln2[(size_t)NTOK * Cdim];
__device__ float g_hh [(size_t)NTOK * HID];    // FC1+GELU output

// ---------------------------------------------------------------------------
// Kernel 1: LN1 + cyclic shift + window partition
// One warp per output window-token.
// ---------------------------------------------------------------------------
__global__ void ln1_window_kernel(const float* __restrict__ x,
                                  const float* __restrict__ g1,
                                  const float* __restrict__ b1,
                                  float* __restrict__ out)
{
    const int warp = threadIdx.x >> 5;
    const int lane = threadIdx.x & 31;
    const long t = (long)blockIdx.x * 8 + warp;   // token in window layout
    const int b_ = (int)(t >> 6);
    const int n  = (int)(t & 63);
    const int b  = b_ >> 8;
    const int wi = b_ & 255;
    const int wh = wi >> 4, ww = wi & 15;
    const int sh = wh * 8 + (n >> 3);
    const int sw = ww * 8 + (n & 7);
    const int h  = (sh + SHIFT) & 127;
    const int w  = (sw + SHIFT) & 127;
    const float* src = x + (((long)b * 128 + h) * 128 + w) * Cdim;

    float v[6];
    float s = 0.f, ss = 0.f;
#pragma unroll
    for (int i = 0; i < 6; i++) {
        v[i] = src[lane + 32 * i];
        s  += v[i];
        ss += v[i] * v[i];
    }
#pragma unroll
    for (int o = 16; o > 0; o >>= 1) {
        s  += __shfl_xor_sync(0xffffffffu, s,  o);
        ss += __shfl_xor_sync(0xffffffffu, ss, o);
    }
    const float mu  = s * (1.f / Cdim);
    const float var = ss * (1.f / Cdim) - mu * mu;
    const float r   = rsqrtf(var + 1e-5f);
    float* dst = out + t * Cdim;
#pragma unroll
    for (int i = 0; i < 6; i++) {
        const int c = lane + 32 * i;
        dst[c] = (v[i] - mu) * r * g1[c] + b1[c];
    }
}

// ---------------------------------------------------------------------------
// Generic SGEMM: C[M,N] = A[M,K] * B[N,K]^T + bias
// EPI: 0 = bias only, 1 = bias+GELU(exact), 2 = bias + residual add
// 128x128 tile, BK=8, 256 threads, 8x8 microtile.
// ---------------------------------------------------------------------------
template <int EPI>
__global__ void __launch_bounds__(256)
sgemm_kernel(const float* __restrict__ A, const float* __restrict__ B,
             const float* __restrict__ bias, const float* __restrict__ res,
             float* __restrict__ C, int M, int N, int K)
{
    __shared__ float As[8][128];
    __shared__ float Bs[8][128];

    const int tid = threadIdx.x;
    const int tx = tid & 15;
    const int ty = tid >> 4;
    const long m0 = (long)blockIdx.y * 128;
    const int  n0 = blockIdx.x * 128;

    const int lr = tid >> 1;        // 0..127
    const int lc = (tid & 1) << 2;  // 0 or 4
    const float* Ap = A + (m0 + lr) * K + lc;
    const float* Bp = B + (long)(n0 + lr) * K + lc;
    const bool bok = (n0 + lr) < N;

    float acc[8][8];
#pragma unroll
    for (int i = 0; i < 8; i++)
#pragma unroll
        for (int j = 0; j < 8; j++) acc[i][j] = 0.f;

    for (int k0 = 0; k0 < K; k0 += 8) {
        float4 a4 = *(const float4*)(Ap + k0);
        float4 b4 = bok ? *(const float4*)(Bp + k0) : make_float4(0.f, 0.f, 0.f, 0.f);
        As[lc + 0][lr] = a4.x; As[lc + 1][lr] = a4.y;
        As[lc + 2][lr] = a4.z; As[lc + 3][lr] = a4.w;
        Bs[lc + 0][lr] = b4.x; Bs[lc + 1][lr] = b4.y;
        Bs[lc + 2][lr] = b4.z; Bs[lc + 3][lr] = b4.w;
        __syncthreads();
#pragma unroll
        for (int kk = 0; kk < 8; kk++) {
            float ra[8], rb[8];
            *(float4*)(ra)     = *(const float4*)&As[kk][ty * 8];
            *(float4*)(ra + 4) = *(const float4*)&As[kk][ty * 8 + 4];
            *(float4*)(rb)     = *(const float4*)&Bs[kk][tx * 8];
            *(float4*)(rb + 4) = *(const float4*)&Bs[kk][tx * 8 + 4];
#pragma unroll
            for (int i = 0; i < 8; i++)
#pragma unroll
                for (int j = 0; j < 8; j++)
                    acc[i][j] += ra[i] * rb[j];
        }
        __syncthreads();
    }

#pragma unroll
    for (int i = 0; i < 8; i++) {
        const long m = m0 + ty * 8 + i;
#pragma unroll
        for (int j = 0; j < 8; j++) {
            const int n = n0 + tx * 8 + j;
            if (n < N) {
                float v = acc[i][j] + bias[n];
                if (EPI == 1) {
                    v = 0.5f * v * (1.f + erff(v * 0.7071067811865475f));
                } else if (EPI == 2) {
                    v += res[m * N + n];
                }
                C[m * N + n] = v;
            }
        }
    }
}

// ---------------------------------------------------------------------------
// Kernel 3: fused window attention. One block per (window, head), 64 threads.
// ---------------------------------------------------------------------------
__global__ void attn_kernel(const float* __restrict__ qkv,
                            const float* __restrict__ rpb,
                            float* __restrict__ out)
{
    const int win  = blockIdx.x;   // 0..2047
    const int head = blockIdx.y;   // 0..5
    const int n    = threadIdx.x;  // 0..63

    __shared__ float ks[64][33];
    __shared__ float vs[64][33];
    __shared__ float sp[64][65];
    __shared__ float sbias[225];
    __shared__ int   lab[64];

    const float* base = qkv + (long)win * NPW * (3 * Cdim);

    // load K and V rows for this head
    const float* krow = base + n * (3 * Cdim) + Cdim + head * HD;
    const float* vrow = base + n * (3 * Cdim) + 2 * Cdim + head * HD;
#pragma unroll
    for (int d = 0; d < HD; d++) {
        ks[n][d] = krow[d];
        vs[n][d] = vrow[d];
    }

    // relative-position bias slice for this head
    for (int idx = n; idx < 225; idx += 64)
        sbias[idx] = rpb[idx * NH + head];

    // shift-mask region label for this token
    {
        const int wi = win & 255;
        const int wh = wi >> 4, ww = wi & 15;
        const int gh = wh * 8 + (n >> 3);
        const int gw = ww * 8 + (n & 7);
        const int rh = (gh < Himg - WS) ? 0 : ((gh < Himg - SHIFT) ? 1 : 2);
        const int rw = (gw < Wimg - WS) ? 0 : ((gw < Wimg - SHIFT) ? 1 : 2);
        lab[n] = rh * 3 + rw;
    }
    __syncthreads();

    // Q row in registers (scaled)
    float q[HD];
    const float* qrow = base + n * (3 * Cdim) + head * HD;
#pragma unroll
    for (int d = 0; d < HD; d++) q[d] = qrow[d] * 0.17677669529663687f; // 1/sqrt(32)

    const int i = n >> 3, j = n & 7;
    const int myl = lab[n];

    float mx = -1e30f;
    for (int m = 0; m < 64; m++) {
        float s = 0.f;
#pragma unroll
        for (int d = 0; d < HD; d++) s += q[d] * ks[m][d];
        const int i2 = m >> 3, j2 = m & 7;
        s += sbias[(i - i2 + 7) * 15 + (j - j2 + 7)];
        if (lab[m] != myl) s -= 100.f;
        sp[n][m] = s;
        mx = fmaxf(mx, s);
    }

    float sum = 0.f;
    for (int m = 0; m < 64; m++) {
        const float e = expf(sp[n][m] - mx);
        sp[n][m] = e;
        sum += e;
    }
    const float inv = 1.f / sum;

    float accv[HD];
#pragma unroll
    for (int d = 0; d < HD; d++) accv[d] = 0.f;
    for (int m = 0; m < 64; m++) {
        const float p = sp[n][m];
#pragma unroll
        for (int d = 0; d < HD; d++) accv[d] += p * vs[m][d];
    }

    float* dst = out + ((long)win * NPW + n) * Cdim + head * HD;
#pragma unroll
    for (int d = 0; d < HD; d++) dst[d] = accv[d] * inv;
}

// ---------------------------------------------------------------------------
// Kernel 5: window reverse + unshift + residual add + LN2
// One warp per original-layout token.
// ---------------------------------------------------------------------------
__global__ void unshift_add_ln2_kernel(const float* __restrict__ x,
                                       const float* __restrict__ proj,
                                       const float* __restrict__ g2,
                                       const float* __restrict__ b2,
                                       float* __restrict__ x1,
                                       float* __restrict__ ln2)
{
    const int warp = threadIdx.x >> 5;
    const int lane = threadIdx.x & 31;
    const long t = (long)blockIdx.x * 8 + warp;   // original layout token
    const int b  = (int)(t >> 14);
    const int hw = (int)(t & 16383);
    const int h  = hw >> 7, w = hw & 127;
    const int sh = (h + 128 - SHIFT) & 127;
    const int sw = (w + 128 - SHIFT) & 127;
    const int wh = sh >> 3, ii = sh & 7;
    const int ww = sw >> 3, jj = sw & 7;
    const long wt = (((long)b * 256 + wh * 16 + ww) * 64 + ii * 8 + jj);

    const float* xs = x    + t  * Cdim;
    const float* ps = proj + wt * Cdim;

    float v[6];
    float s = 0.f, ss = 0.f;
#pragma unroll
    for (int i = 0; i < 6; i++) {
        const int c = lane + 32 * i;
        v[i] = xs[c] + ps[c];
        s  += v[i];
        ss += v[i] * v[i];
    }
    float* x1p = x1 + t * Cdim;
#pragma unroll
    for (int i = 0; i < 6; i++) x1p[lane + 32 * i] = v[i];

#pragma unroll
    for (int o = 16; o > 0; o >>= 1) {
        s  += __shfl_xor_sync(0xffffffffu, s,  o);
        ss += __shfl_xor_sync(0xffffffffu, ss, o);
    }
    const float mu  = s * (1.f / Cdim);
    const float var = ss * (1.f / Cdim) - mu * mu;
    const float r   = rsqrtf(var + 1e-5f);
    float* lp = ln2 + t * Cdim;
#pragma unroll
    for (int i = 0; i < 6; i++) {
        const int c = lane + 32 * i;
        lp[c] = (v[i] - mu) * r * g2[c] + b2[c];
    }
}

// ---------------------------------------------------------------------------
// Launch
// ---------------------------------------------------------------------------
extern "C" void kernel_launch(void* const* d_in, const int* in_sizes, int n_in,
                              void* d_out, int out_size)
{
    const float* x      = (const float*)d_in[0];
    const float* g1     = (const float*)d_in[1];
    const float* b1     = (const float*)d_in[2];
    const float* qkv_w  = (const float*)d_in[3];
    const float* qkv_b  = (const float*)d_in[4];
    const float* rpb    = (const float*)d_in[5];
    const float* proj_w = (const float*)d_in[6];
    const float* proj_b = (const float*)d_in[7];
    const float* g2     = (const float*)d_in[8];
    const float* b2     = (const float*)d_in[9];
    const float* fc1_w  = (const float*)d_in[10];
    const float* fc1_b  = (const float*)d_in[11];
    const float* fc2_w  = (const float*)d_in[12];
    const float* fc2_b  = (const float*)d_in[13];
    float* out = (float*)d_out;

    float *p_win, *p_qkv, *p_att, *p_x1, *p_ln2, *p_hh;
    cudaGetSymbolAddress((void**)&p_win, g_win);
    cudaGetSymbolAddress((void**)&p_qkv, g_qkv);
    cudaGetSymbolAddress((void**)&p_att, g_att);
    cudaGetSymbolAddress((void**)&p_x1,  g_x1);
    cudaGetSymbolAddress((void**)&p_ln2, g_ln2);
    cudaGetSymbolAddress((void**)&p_hh,  g_hh);

    const int M = NTOK;  // 131072

    // 1. LN1 + shift + window
    ln1_window_kernel<<<M / 8, 256>>>(x, g1, b1, p_win);

    // 2. QKV GEMM: [M,576] = win[M,192] @ qkv_w^T
    {
        dim3 grid((3 * Cdim + 127) / 128, M / 128);
        sgemm_kernel<0><<<grid, 256>>>(p_win, qkv_w, qkv_b, nullptr, p_qkv,
                                       M, 3 * Cdim, Cdim);
    }

    // 3. Window attention
    {
        dim3 grid(NWIN, NH);
        attn_kernel<<<grid, 64>>>(p_qkv, rpb, p_att);
    }

    // 4. proj GEMM: [M,192] = att[M,192] @ proj_w^T  (reuses g_win as output)
    {
        dim3 grid((Cdim + 127) / 128, M / 128);
        sgemm_kernel<0><<<grid, 256>>>(p_att, proj_w, proj_b, nullptr, p_win,
                                       M, Cdim, Cdim);
    }

    // 5. unshift + residual + LN2
    unshift_add_ln2_kernel<<<M / 8, 256>>>(x, p_win, g2, b2, p_x1, p_ln2);

    // 6. FC1 GEMM + GELU: [M,768] = ln2[M,192] @ fc1_w^T
    {
        dim3 grid((HID + 127) / 128, M / 128);
        sgemm_kernel<1><<<grid, 256>>>(p_ln2, fc1_w, fc1_b, nullptr, p_hh,
                                       M, HID, Cdim);
    }

    // 7. FC2 GEMM + residual: out[M,192] = hh[M,768] @ fc2_w^T + x1
    {
        dim3 grid((Cdim + 127) / 128, M / 128);
        sgemm_kernel<2><<<grid, 256>>>(p_hh, fc2_w, fc2_b, p_x1, out,
                                       M, Cdim, HID);
    }
}

// round 3
// speedup vs baseline: 2.4868x; 2.4868x over previous
#include <cuda_runtime.h>
#include <math.h>
#include <stdint.h>

// ---------------------------------------------------------------------------
// Problem constants
// ---------------------------------------------------------------------------
#define Bsz   8
#define Himg  128
#define Wimg  128
#define Cdim  192
#define HID   768
#define WS    8
#define SHIFT 4
#define NH    6
#define HD    32
#define NTOK  (Bsz*Himg*Wimg)             // 131072
#define NWIN  (Bsz*(Himg/WS)*(Wimg/WS))   // 2048
#define NPW   (WS*WS)                     // 64

// ---------------------------------------------------------------------------
// Scratch
// ---------------------------------------------------------------------------
__device__ __align__(16) float g_win[(size_t)NTOK * Cdim];
__device__ __align__(16) float g_qkv[(size_t)NTOK * 3 * Cdim];
__device__ __align__(16) float g_att[(size_t)NTOK * Cdim];
__device__ __align__(16) float g_x1 [(size_t)NTOK * Cdim];
__device__ __align__(16) float g_ln2[(size_t)NTOK * Cdim];
__device__ __align__(16) float g_hh [(size_t)NTOK * HID];
// rounded weights: qkv @0, proj @110592, fc1 @147456, fc2 @294912
__device__ __align__(16) float g_wr[442368];

// ---------------------------------------------------------------------------
// Helpers
// ---------------------------------------------------------------------------
__device__ __forceinline__ uint32_t smem_u32(const void* p) {
    uint32_t a;
    asm("{ .reg .u64 t; cvta.to.shared.u64 t, %1; cvt.u32.u64 %0, t; }" : "=r"(a) : "l"(p));
    return a;
}
__device__ __forceinline__ uint32_t tf32r(float v) {
    uint32_t u;
    asm("cvt.rna.tf32.f32 %0, %1;" : "=r"(u) : "f"(v));
    return u;
}
__device__ __forceinline__ float tf32f(float v) {
    return __uint_as_float(tf32r(v));
}
__device__ __forceinline__ void cp_async16(uint32_t dst, const void* src) {
    asm volatile("cp.async.cg.shared.global [%0], [%1], 16;" :: "r"(dst), "l"(src) : "memory");
}
__device__ __forceinline__ uint32_t lds32(uint32_t addr) {
    uint32_t v;
    asm volatile("ld.shared.b32 %0, [%1];" : "=r"(v) : "r"(addr));
    return v;
}
__device__ __forceinline__ void mma8(float* c, const uint32_t* a, const uint32_t* b) {
    asm volatile("mma.sync.aligned.m16n8k8.row.col.f32.tf32.tf32.f32 "
        "{%0,%1,%2,%3}, {%4,%5,%6,%7}, {%8,%9}, {%0,%1,%2,%3};"
        : "+f"(c[0]), "+f"(c[1]), "+f"(c[2]), "+f"(c[3])
        : "r"(a[0]), "r"(a[1]), "r"(a[2]), "r"(a[3]), "r"(b[0]), "r"(b[1]));
}

// ---------------------------------------------------------------------------
// tf32 mma.sync GEMM: C[M,N] = A[M,K] @ B[N,K]^T + bias (+EPI)
// CTA tile 128x192, BK=32, 256 threads (8 warps, 2m x 4n), warp tile 64x48.
// EPI: 0 bias, 1 bias+GELU, 2 bias+residual. ROUND: tf32-round outputs.
// Inputs A, B must already be tf32-rounded values (fp32 bit patterns).
// ---------------------------------------------------------------------------
#define ASTAGE_BYTES 16384          // 128*32*4
#define BSTAGE_BYTES 24576          // 192*32*4
#define STAGE_BYTES  (ASTAGE_BYTES + BSTAGE_BYTES)
#define GEMM_SMEM    (2*STAGE_BYTES + 128)

template <int EPI, int ROUND>
__global__ void __launch_bounds__(256, 1)
gemm_mma(const float* __restrict__ A, const float* __restrict__ B,
         const float* __restrict__ bias, const float* __restrict__ res,
         float* __restrict__ C, int N, int K)
{
    extern __shared__ char dsm[];
    const uint32_t base = (smem_u32(dsm) + 127u) & ~127u;

    const int tid  = threadIdx.x;
    const int wid  = tid >> 5;
    const int lane = tid & 31;
    const int g    = lane >> 2;       // 0..7
    const int tig  = lane & 3;        // 0..3
    const int wm   = wid >> 2;        // 0..1
    const int wn   = wid & 3;         // 0..3
    const int m0w  = wm * 64;
    const int n0w  = wn * 48;

    const long m0 = (long)blockIdx.x * 128;
    const int  n0 = blockIdx.y * 192;

    // global source pointers for cp.async
    const int lm = tid >> 3;          // 0..31 (row within 32-row group)
    const int lq = tid & 7;           // float4 slot within row
    const float* srcA = A + (m0 + lm) * K + lq * 4;
    const float* srcB = B + (long)(n0 + lm) * K + lq * 4;
    const uint32_t swz = (uint32_t)((lq ^ (lm & 7)) << 4);   // constant per thread
    const uint32_t dstA0 = base + (uint32_t)lm * 128 + swz;
    const uint32_t dstB0 = base + ASTAGE_BYTES + (uint32_t)lm * 128 + swz;

    float acc[4][6][4];
#pragma unroll
    for (int mi = 0; mi < 4; mi++)
#pragma unroll
        for (int ni = 0; ni < 6; ni++)
#pragma unroll
            for (int c = 0; c < 4; c++) acc[mi][ni][c] = 0.f;

    const int NC = K >> 5;

    // issue stage loads (stage buffer sel, k-chunk index)
#define ISSUE(buf, kc_) do { \
        const uint32_t so = (uint32_t)(buf) * STAGE_BYTES; \
        const float* sa = srcA + (kc_); \
        const float* sb = srcB + (kc_); \
        _Pragma("unroll") \
        for (int it = 0; it < 4; it++) \
            cp_async16(dstA0 + so + it * 4096, sa + (long)it * 32 * K); \
        _Pragma("unroll") \
        for (int it = 0; it < 6; it++) \
            cp_async16(dstB0 + so + it * 4096, sb + (long)it * 32 * K); \
        asm volatile("cp.async.commit_group;" ::: "memory"); \
    } while (0)

    ISSUE(0, 0);

    // per-warp fragment base addresses (within stage 0)
    const uint32_t aRow0 = base + (uint32_t)(m0w + g) * 128 + (uint32_t)tig * 4;
    const uint32_t bRow0 = base + ASTAGE_BYTES + (uint32_t)(n0w + g) * 128 + (uint32_t)tig * 4;

    for (int i = 0; i < NC; i++) {
        if (i + 1 < NC) {
            ISSUE((i + 1) & 1, (i + 1) << 5);
            asm volatile("cp.async.wait_group 1;" ::: "memory");
        } else {
            asm volatile("cp.async.wait_group 0;" ::: "memory");
        }
        __syncthreads();

        const uint32_t so = (uint32_t)(i & 1) * STAGE_BYTES;
        const uint32_t aRow = aRow0 + so;
        const uint32_t bRow = bRow0 + so;

#pragma unroll
        for (int s = 0; s < 4; s++) {
            const uint32_t koff0 = (uint32_t)(((2 * s) ^ g) << 4);
            const uint32_t koff1 = koff0 ^ 16u;

            uint32_t af[4][4];
#pragma unroll
            for (int mi = 0; mi < 4; mi++) {
                const uint32_t p = aRow + mi * 2048;
                af[mi][0] = lds32(p + koff0);
                af[mi][1] = lds32(p + 1024 + koff0);
                af[mi][2] = lds32(p + koff1);
                af[mi][3] = lds32(p + 1024 + koff1);
            }
            uint32_t bf[6][2];
#pragma unroll
            for (int ni = 0; ni < 6; ni++) {
                const uint32_t p = bRow + ni * 1024;
                bf[ni][0] = lds32(p + koff0);
                bf[ni][1] = lds32(p + koff1);
            }
#pragma unroll
            for (int mi = 0; mi < 4; mi++)
#pragma unroll
                for (int ni = 0; ni < 6; ni++)
                    mma8(acc[mi][ni], af[mi], bf[ni]);
        }
        __syncthreads();
    }
#undef ISSUE

    // Epilogue
#pragma unroll
    for (int mi = 0; mi < 4; mi++) {
        const long r0 = m0 + m0w + mi * 16 + g;
        const long r1 = r0 + 8;
#pragma unroll
        for (int ni = 0; ni < 6; ni++) {
            const int col = n0 + n0w + ni * 8 + 2 * tig;
            const float b0 = bias[col], b1 = bias[col + 1];
            float v0 = acc[mi][ni][0] + b0;
            float v1 = acc[mi][ni][1] + b1;
            float v2 = acc[mi][ni][2] + b0;
            float v3 = acc[mi][ni][3] + b1;
            if (EPI == 1) {
                v0 = 0.5f * v0 * (1.f + erff(v0 * 0.7071067811865475f));
                v1 = 0.5f * v1 * (1.f + erff(v1 * 0.7071067811865475f));
                v2 = 0.5f * v2 * (1.f + erff(v2 * 0.7071067811865475f));
                v3 = 0.5f * v3 * (1.f + erff(v3 * 0.7071067811865475f));
            } else if (EPI == 2) {
                const float2 ra = *(const float2*)(res + r0 * N + col);
                const float2 rb = *(const float2*)(res + r1 * N + col);
                v0 += ra.x; v1 += ra.y; v2 += rb.x; v3 += rb.y;
            }
            if (ROUND) {
                v0 = tf32f(v0); v1 = tf32f(v1); v2 = tf32f(v2); v3 = tf32f(v3);
            }
            *(float2*)(C + r0 * N + col) = make_float2(v0, v1);
            *(float2*)(C + r1 * N + col) = make_float2(v2, v3);
        }
    }
}

// ---------------------------------------------------------------------------
// Weight rounding (tf32) prep
// ---------------------------------------------------------------------------
__global__ void round_kernel(const float* __restrict__ src, float* __restrict__ dst, int n)
{
    const int i = blockIdx.x * 1024 + threadIdx.x * 4;
    if (i + 3 < n) {
        float4 v = *(const float4*)(src + i);
        v.x = tf32f(v.x); v.y = tf32f(v.y); v.z = tf32f(v.z); v.w = tf32f(v.w);
        *(float4*)(dst + i) = v;
    } else {
        for (int j = i; j < n; j++) dst[j] = tf32f(src[j]);
    }
}

// ---------------------------------------------------------------------------
// Kernel 1: LN1 + cyclic shift + window partition (one warp / token)
// output tf32-rounded (feeds qkv GEMM)
// ---------------------------------------------------------------------------
__global__ void ln1_window_kernel(const float* __restrict__ x,
                                  const float* __restrict__ g1,
                                  const float* __restrict__ b1,
                                  float* __restrict__ out)
{
    const int warp = threadIdx.x >> 5;
    const int lane = threadIdx.x & 31;
    const long t = (long)blockIdx.x * 8 + warp;
    const int b_ = (int)(t >> 6);
    const int n  = (int)(t & 63);
    const int b  = b_ >> 8;
    const int wi = b_ & 255;
    const int h  = ((wi >> 4) * 8 + (n >> 3) + SHIFT) & 127;
    const int w  = ((wi & 15) * 8 + (n & 7) + SHIFT) & 127;
    const float* src = x + (((long)b * 128 + h) * 128 + w) * Cdim;

    float v[6];
    float s = 0.f, ss = 0.f;
#pragma unroll
    for (int i = 0; i < 6; i++) {
        v[i] = src[lane + 32 * i];
        s += v[i]; ss += v[i] * v[i];
    }
#pragma unroll
    for (int o = 16; o > 0; o >>= 1) {
        s  += __shfl_xor_sync(0xffffffffu, s,  o);
        ss += __shfl_xor_sync(0xffffffffu, ss, o);
    }
    const float mu  = s * (1.f / Cdim);
    const float var = ss * (1.f / Cdim) - mu * mu;
    const float r   = rsqrtf(var + 1e-5f);
    float* dst = out + t * Cdim;
#pragma unroll
    for (int i = 0; i < 6; i++) {
        const int c = lane + 32 * i;
        dst[c] = tf32f((v[i] - mu) * r * g1[c] + b1[c]);
    }
}

// ---------------------------------------------------------------------------
// Fused window attention (one block per (window, head), 64 threads)
// output tf32-rounded (feeds proj GEMM)
// ---------------------------------------------------------------------------
__global__ void attn_kernel(const float* __restrict__ qkv,
                            const float* __restrict__ rpb,
                            float* __restrict__ out)
{
    const int win  = blockIdx.x;
    const int head = blockIdx.y;
    const int n    = threadIdx.x;

    __shared__ float ks[64][33];
    __shared__ float vs[64][33];
    __shared__ float sp[64][65];
    __shared__ float sbias[225];
    __shared__ int   lab[64];

    const float* base = qkv + (long)win * NPW * (3 * Cdim);
    const float* krow = base + n * (3 * Cdim) + Cdim + head * HD;
    const float* vrow = base + n * (3 * Cdim) + 2 * Cdim + head * HD;
#pragma unroll
    for (int d = 0; d < HD; d++) { ks[n][d] = krow[d]; vs[n][d] = vrow[d]; }
    for (int idx = n; idx < 225; idx += 64) sbias[idx] = rpb[idx * NH + head];
    {
        const int wi = win & 255;
        const int gh = (wi >> 4) * 8 + (n >> 3);
        const int gw = (wi & 15) * 8 + (n & 7);
        const int rh = (gh < Himg - WS) ? 0 : ((gh < Himg - SHIFT) ? 1 : 2);
        const int rw = (gw < Wimg - WS) ? 0 : ((gw < Wimg - SHIFT) ? 1 : 2);
        lab[n] = rh * 3 + rw;
    }
    __syncthreads();

    float q[HD];
    const float* qrow = base + n * (3 * Cdim) + head * HD;
#pragma unroll
    for (int d = 0; d < HD; d++) q[d] = qrow[d] * 0.17677669529663687f;

    const int i = n >> 3, j = n & 7;
    const int myl = lab[n];

    float mx = -1e30f;
    for (int m = 0; m < 64; m++) {
        float s = 0.f;
#pragma unroll
        for (int d = 0; d < HD; d++) s += q[d] * ks[m][d];
        s += sbias[(i - (m >> 3) + 7) * 15 + (j - (m & 7) + 7)];
        if (lab[m] != myl) s -= 100.f;
        sp[n][m] = s;
        mx = fmaxf(mx, s);
    }
    float sum = 0.f;
    for (int m = 0; m < 64; m++) {
        const float e = expf(sp[n][m] - mx);
        sp[n][m] = e; sum += e;
    }
    const float inv = 1.f / sum;

    float accv[HD];
#pragma unroll
    for (int d = 0; d < HD; d++) accv[d] = 0.f;
    for (int m = 0; m < 64; m++) {
        const float p = sp[n][m];
#pragma unroll
        for (int d = 0; d < HD; d++) accv[d] += p * vs[m][d];
    }
    float* dst = out + ((long)win * NPW + n) * Cdim + head * HD;
#pragma unroll
    for (int d = 0; d < HD; d++) dst[d] = tf32f(accv[d] * inv);
}

// ---------------------------------------------------------------------------
// Kernel 5: window reverse + unshift + residual + LN2 (one warp / token)
// ln2 output tf32-rounded (feeds fc1); x1 exact
// ---------------------------------------------------------------------------
__global__ void unshift_add_ln2_kernel(const float* __restrict__ x,
                                       const float* __restrict__ proj,
                                       const float* __restrict__ g2,
                                       const float* __restrict__ b2,
                                       float* __restrict__ x1,
                                       float* __restrict__ ln2)
{
    const int warp = threadIdx.x >> 5;
    const int lane = threadIdx.x & 31;
    const long t = (long)blockIdx.x * 8 + warp;
    const int b  = (int)(t >> 14);
    const int hw = (int)(t & 16383);
    const int h  = hw >> 7, w = hw & 127;
    const int sh = (h + 128 - SHIFT) & 127;
    const int sw = (w + 128 - SHIFT) & 127;
    const long wt = (((long)b * 256 + (sh >> 3) * 16 + (sw >> 3)) * 64 + (sh & 7) * 8 + (sw & 7));

    const float* xs = x    + t  * Cdim;
    const float* ps = proj + wt * Cdim;

    float v[6];
    float s = 0.f, ss = 0.f;
#pragma unroll
    for (int i = 0; i < 6; i++) {
        const int c = lane + 32 * i;
        v[i] = xs[c] + ps[c];
        s += v[i]; ss += v[i] * v[i];
    }
    float* x1p = x1 + t * Cdim;
#pragma unroll
    for (int i = 0; i < 6; i++) x1p[lane + 32 * i] = v[i];
#pragma unroll
    for (int o = 16; o > 0; o >>= 1) {
        s  += __shfl_xor_sync(0xffffffffu, s,  o);
        ss += __shfl_xor_sync(0xffffffffu, ss, o);
    }
    const float mu  = s * (1.f / Cdim);
    const float var = ss * (1.f / Cdim) - mu * mu;
    const float r   = rsqrtf(var + 1e-5f);
    float* lp = ln2 + t * Cdim;
#pragma unroll
    for (int i = 0; i < 6; i++) {
        const int c = lane + 32 * i;
        lp[c] = tf32f((v[i] - mu) * r * g2[c] + b2[c]);
    }
}

// ---------------------------------------------------------------------------
// Launch
// ---------------------------------------------------------------------------
extern "C" void kernel_launch(void* const* d_in, const int* in_sizes, int n_in,
                              void* d_out, int out_size)
{
    const float* x      = (const float*)d_in[0];
    const float* g1     = (const float*)d_in[1];
    const float* b1     = (const float*)d_in[2];
    const float* qkv_w  = (const float*)d_in[3];
    const float* qkv_b  = (const float*)d_in[4];
    const float* rpb    = (const float*)d_in[5];
    const float* proj_w = (const float*)d_in[6];
    const float* proj_b = (const float*)d_in[7];
    const float* g2     = (const float*)d_in[8];
    const float* b2     = (const float*)d_in[9];
    const float* fc1_w  = (const float*)d_in[10];
    const float* fc1_b  = (const float*)d_in[11];
    const float* fc2_w  = (const float*)d_in[12];
    const float* fc2_b  = (const float*)d_in[13];
    float* out = (float*)d_out;

    float *p_win, *p_qkv, *p_att, *p_x1, *p_ln2, *p_hh, *p_wr;
    cudaGetSymbolAddress((void**)&p_win, g_win);
    cudaGetSymbolAddress((void**)&p_qkv, g_qkv);
    cudaGetSymbolAddress((void**)&p_att, g_att);
    cudaGetSymbolAddress((void**)&p_x1,  g_x1);
    cudaGetSymbolAddress((void**)&p_ln2, g_ln2);
    cudaGetSymbolAddress((void**)&p_hh,  g_hh);
    cudaGetSymbolAddress((void**)&p_wr,  g_wr);

    static bool attr_set = false;
    if (!attr_set) {
        cudaFuncSetAttribute(gemm_mma<0,0>, cudaFuncAttributeMaxDynamicSharedMemorySize, GEMM_SMEM);
        cudaFuncSetAttribute(gemm_mma<1,1>, cudaFuncAttributeMaxDynamicSharedMemorySize, GEMM_SMEM);
        cudaFuncSetAttribute(gemm_mma<2,0>, cudaFuncAttributeMaxDynamicSharedMemorySize, GEMM_SMEM);
        attr_set = true;
    }

    float* w_qkv = p_wr;
    float* w_prj = p_wr + 110592;
    float* w_fc1 = p_wr + 147456;
    float* w_fc2 = p_wr + 294912;

    // 0. round weights to tf32
    round_kernel<<<(110592 + 1023) / 1024, 256>>>(qkv_w,  w_qkv, 110592);
    round_kernel<<<( 36864 + 1023) / 1024, 256>>>(proj_w, w_prj,  36864);
    round_kernel<<<(147456 + 1023) / 1024, 256>>>(fc1_w,  w_fc1, 147456);
    round_kernel<<<(147456 + 1023) / 1024, 256>>>(fc2_w,  w_fc2, 147456);

    const int M = NTOK;  // 131072, M tiles = 1024

    // 1. LN1 + shift + window (tf32-rounded out)
    ln1_window_kernel<<<M / 8, 256>>>(x, g1, b1, p_win);

    // 2. QKV: [M,576]
    gemm_mma<0,0><<<dim3(M / 128, 3), 256, GEMM_SMEM>>>(
        p_win, w_qkv, qkv_b, nullptr, p_qkv, 3 * Cdim, Cdim);

    // 3. Window attention (tf32-rounded out)
    attn_kernel<<<dim3(NWIN, NH), 64>>>(p_qkv, rpb, p_att);

    // 4. proj: [M,192]
    gemm_mma<0,0><<<dim3(M / 128, 1), 256, GEMM_SMEM>>>(
        p_att, w_prj, proj_b, nullptr, p_win, Cdim, Cdim);

    // 5. unshift + residual + LN2
    unshift_add_ln2_kernel<<<M / 8, 256>>>(x, p_win, g2, b2, p_x1, p_ln2);

    // 6. FC1 + GELU: [M,768] (tf32-rounded out)
    gemm_mma<1,1><<<dim3(M / 128, 4), 256, GEMM_SMEM>>>(
        p_ln2, w_fc1, fc1_b, nullptr, p_hh, HID, Cdim);

    // 7. FC2 + residual: out = hh @ fc2_w^T + x1
    gemm_mma<2,0><<<dim3(M / 128, 1), 256, GEMM_SMEM>>>(
        p_hh, w_fc2, fc2_b, p_x1, out, Cdim, HID);
}

// round 4
// speedup vs baseline: 2.9149x; 1.1722x over previous
#include <cuda_runtime.h>
#include <cuda_fp16.h>
#include <math.h>
#include <stdint.h>

// ---------------------------------------------------------------------------
// Problem constants
// ---------------------------------------------------------------------------
#define Bsz   8
#define Himg  128
#define Wimg  128
#define Cdim  192
#define HID   768
#define WS    8
#define SHIFT 4
#define NH    6
#define HD    32
#define NTOK  (Bsz*Himg*Wimg)             // 131072
#define NWIN  (Bsz*(Himg/WS)*(Wimg/WS))   // 2048
#define NPW   (WS*WS)                     // 64

// ---------------------------------------------------------------------------
// Scratch
// ---------------------------------------------------------------------------
__device__ __align__(16) __half g_win[(size_t)NTOK * Cdim];
__device__ __align__(16) __half g_qkv[(size_t)NTOK * 3 * Cdim];
__device__ __align__(16) __half g_att[(size_t)NTOK * Cdim];
__device__ __align__(16) __half g_ln2[(size_t)NTOK * Cdim];
__device__ __align__(16) __half g_hh [(size_t)NTOK * HID];
__device__ __align__(16) float  g_x1 [(size_t)NTOK * Cdim];
__device__ __align__(16) float  g_proj[(size_t)NTOK * Cdim];
// half weights: qkv @0, proj @110592, fc1 @147456, fc2 @294912
__device__ __align__(16) __half g_wh[442368];

// ---------------------------------------------------------------------------
// Helpers
// ---------------------------------------------------------------------------
__device__ __forceinline__ uint32_t smem_u32(const void* p) {
    uint32_t a;
    asm("{ .reg .u64 t; cvta.to.shared.u64 t, %1; cvt.u32.u64 %0, t; }" : "=r"(a) : "l"(p));
    return a;
}
__device__ __forceinline__ void cp_async16(uint32_t dst, const void* src) {
    asm volatile("cp.async.cg.shared.global [%0], [%1], 16;" :: "r"(dst), "l"(src) : "memory");
}
__device__ __forceinline__ uint32_t lds32(uint32_t addr) {
    uint32_t v;
    asm volatile("ld.shared.b32 %0, [%1];" : "=r"(v) : "r"(addr));
    return v;
}
__device__ __forceinline__ void mma16(float* c, const uint32_t* a, const uint32_t* b) {
    asm volatile("mma.sync.aligned.m16n8k16.row.col.f32.f16.f16.f32 "
        "{%0,%1,%2,%3}, {%4,%5,%6,%7}, {%8,%9}, {%0,%1,%2,%3};"
        : "+f"(c[0]), "+f"(c[1]), "+f"(c[2]), "+f"(c[3])
        : "r"(a[0]), "r"(a[1]), "r"(a[2]), "r"(a[3]), "r"(b[0]), "r"(b[1]));
}

// ---------------------------------------------------------------------------
// fp16 mma.sync GEMM: C[M,N] = A[M,K] @ B[N,K]^T + bias (+EPI)
// CTA tile 128x192, BK=64 halves, 256 threads (8 warps 2x4), warp tile 64x48.
// A,B half. EPI: 0 bias, 1 bias+GELU, 2 bias+residual(fp32).
// OUTH: 1 -> write half, 0 -> write float.
// ---------------------------------------------------------------------------
#define ASTAGE 16384          // 128*64*2
#define BSTAGE 24576          // 192*64*2
#define STAGE  (ASTAGE + BSTAGE)
#define GEMM_SMEM (2*STAGE + 128)

template <int EPI, int OUTH>
__global__ void __launch_bounds__(256, 1)
gemm_h(const __half* __restrict__ A, const __half* __restrict__ B,
       const float* __restrict__ bias, const float* __restrict__ res,
       void* __restrict__ Cv, int N, int K)
{
    extern __shared__ char dsm[];
    const uint32_t base = (smem_u32(dsm) + 127u) & ~127u;

    const int tid  = threadIdx.x;
    const int wid  = tid >> 5;
    const int lane = tid & 31;
    const int g    = lane >> 2;
    const int tig  = lane & 3;
    const int m0w  = (wid >> 2) * 64;
    const int n0w  = (wid & 3) * 48;

    const long m0 = (long)blockIdx.x * 128;
    const int  n0 = blockIdx.y * 192;

    const int lm = tid >> 3;          // 0..31
    const int lq = tid & 7;           // 16B chunk within 128B row
    const __half* srcA = A + (m0 + lm) * K + lq * 8;
    const __half* srcB = B + (long)(n0 + lm) * K + lq * 8;
    const uint32_t swz = (uint32_t)((lq ^ (lm & 7)) << 4);
    const uint32_t dstA0 = base + (uint32_t)lm * 128 + swz;
    const uint32_t dstB0 = base + ASTAGE + (uint32_t)lm * 128 + swz;

    float acc[4][6][4];
#pragma unroll
    for (int mi = 0; mi < 4; mi++)
#pragma unroll
        for (int ni = 0; ni < 6; ni++)
#pragma unroll
            for (int c = 0; c < 4; c++) acc[mi][ni][c] = 0.f;

    const int NC = K >> 6;

#define ISSUE(buf, kc_) do { \
        const uint32_t so = (uint32_t)(buf) * STAGE; \
        const __half* sa = srcA + (kc_); \
        const __half* sb = srcB + (kc_); \
        _Pragma("unroll") \
        for (int it = 0; it < 4; it++) \
            cp_async16(dstA0 + so + it * 4096, sa + (long)it * 32 * K); \
        _Pragma("unroll") \
        for (int it = 0; it < 6; it++) \
            cp_async16(dstB0 + so + it * 4096, sb + (long)it * 32 * K); \
        asm volatile("cp.async.commit_group;" ::: "memory"); \
    } while (0)

    ISSUE(0, 0);

    const uint32_t aRow0 = base + (uint32_t)(m0w + g) * 128 + (uint32_t)tig * 4;
    const uint32_t bRow0 = base + ASTAGE + (uint32_t)(n0w + g) * 128 + (uint32_t)tig * 4;

    for (int i = 0; i < NC; i++) {
        if (i + 1 < NC) {
            ISSUE((i + 1) & 1, (i + 1) << 6);
            asm volatile("cp.async.wait_group 1;" ::: "memory");
        } else {
            asm volatile("cp.async.wait_group 0;" ::: "memory");
        }
        __syncthreads();

        const uint32_t so = (uint32_t)(i & 1) * STAGE;
        const uint32_t aRow = aRow0 + so;
        const uint32_t bRow = bRow0 + so;

#pragma unroll
        for (int s = 0; s < 4; s++) {      // 4 k-steps of K=16 halves (32B)
            const uint32_t koff0 = (uint32_t)(((2 * s) ^ g) << 4);
            const uint32_t koff1 = koff0 ^ 16u;

            uint32_t af[4][4];
#pragma unroll
            for (int mi = 0; mi < 4; mi++) {
                const uint32_t p = aRow + mi * 2048;
                af[mi][0] = lds32(p + koff0);
                af[mi][1] = lds32(p + 1024 + koff0);
                af[mi][2] = lds32(p + koff1);
                af[mi][3] = lds32(p + 1024 + koff1);
            }
            uint32_t bf[6][2];
#pragma unroll
            for (int ni = 0; ni < 6; ni++) {
                const uint32_t p = bRow + ni * 1024;
                bf[ni][0] = lds32(p + koff0);
                bf[ni][1] = lds32(p + koff1);
            }
#pragma unroll
            for (int mi = 0; mi < 4; mi++)
#pragma unroll
                for (int ni = 0; ni < 6; ni++)
                    mma16(acc[mi][ni], af[mi], bf[ni]);
        }
        __syncthreads();
    }
#undef ISSUE

    // Epilogue
#pragma unroll
    for (int mi = 0; mi < 4; mi++) {
        const long r0 = m0 + m0w + mi * 16 + g;
        const long r1 = r0 + 8;
#pragma unroll
        for (int ni = 0; ni < 6; ni++) {
            const int col = n0 + n0w + ni * 8 + 2 * tig;
            const float b0 = bias[col], b1 = bias[col + 1];
            float v0 = acc[mi][ni][0] + b0;
            float v1 = acc[mi][ni][1] + b1;
            float v2 = acc[mi][ni][2] + b0;
            float v3 = acc[mi][ni][3] + b1;
            if (EPI == 1) {
                v0 = 0.5f * v0 * (1.f + erff(v0 * 0.7071067811865475f));
                v1 = 0.5f * v1 * (1.f + erff(v1 * 0.7071067811865475f));
                v2 = 0.5f * v2 * (1.f + erff(v2 * 0.7071067811865475f));
                v3 = 0.5f * v3 * (1.f + erff(v3 * 0.7071067811865475f));
            } else if (EPI == 2) {
                const float2 ra = *(const float2*)(res + r0 * N + col);
                const float2 rb = *(const float2*)(res + r1 * N + col);
                v0 += ra.x; v1 += ra.y; v2 += rb.x; v3 += rb.y;
            }
            if (OUTH) {
                __half* C = (__half*)Cv;
                *(__half2*)(C + r0 * N + col) = __floats2half2_rn(v0, v1);
                *(__half2*)(C + r1 * N + col) = __floats2half2_rn(v2, v3);
            } else {
                float* C = (float*)Cv;
                *(float2*)(C + r0 * N + col) = make_float2(v0, v1);
                *(float2*)(C + r1 * N + col) = make_float2(v2, v3);
            }
        }
    }
}

// ---------------------------------------------------------------------------
// Weight fp32 -> fp16
// ---------------------------------------------------------------------------
__global__ void tohalf_kernel(const float* __restrict__ src, __half* __restrict__ dst, int n)
{
    const int i = blockIdx.x * 1024 + threadIdx.x * 4;
    if (i + 3 < n) {
        float4 v = *(const float4*)(src + i);
        __half2* d = (__half2*)(dst + i);
        d[0] = __floats2half2_rn(v.x, v.y);
        d[1] = __floats2half2_rn(v.z, v.w);
    } else {
        for (int j = i; j < n; j++) dst[j] = __float2half_rn(src[j]);
    }
}

// ---------------------------------------------------------------------------
// LN1 + cyclic shift + window partition (one warp / token) -> half
// ---------------------------------------------------------------------------
__global__ void ln1_window_kernel(const float* __restrict__ x,
                                  const float* __restrict__ g1,
                                  const float* __restrict__ b1,
                                  __half* __restrict__ out)
{
    const int warp = threadIdx.x >> 5;
    const int lane = threadIdx.x & 31;
    const long t = (long)blockIdx.x * 8 + warp;
    const int b_ = (int)(t >> 6);
    const int n  = (int)(t & 63);
    const int b  = b_ >> 8;
    const int wi = b_ & 255;
    const int h  = ((wi >> 4) * 8 + (n >> 3) + SHIFT) & 127;
    const int w  = ((wi & 15) * 8 + (n & 7) + SHIFT) & 127;
    const float* src = x + (((long)b * 128 + h) * 128 + w) * Cdim;

    float v[6];
    float s = 0.f, ss = 0.f;
#pragma unroll
    for (int i = 0; i < 6; i++) {
        v[i] = src[lane + 32 * i];
        s += v[i]; ss += v[i] * v[i];
    }
#pragma unroll
    for (int o = 16; o > 0; o >>= 1) {
        s  += __shfl_xor_sync(0xffffffffu, s,  o);
        ss += __shfl_xor_sync(0xffffffffu, ss, o);
    }
    const float mu  = s * (1.f / Cdim);
    const float var = ss * (1.f / Cdim) - mu * mu;
    const float r   = rsqrtf(var + 1e-5f);
    __half* dst = out + t * Cdim;
#pragma unroll
    for (int i = 0; i < 6; i++) {
        const int c = lane + 32 * i;
        dst[c] = __float2half_rn((v[i] - mu) * r * g1[c] + b1[c]);
    }
}

// ---------------------------------------------------------------------------
// Fused window attention (block per (window, head), 64 threads), half in/out
// ---------------------------------------------------------------------------
__global__ void attn_kernel(const __half* __restrict__ qkv,
                            const float* __restrict__ rpb,
                            __half* __restrict__ out)
{
    const int win  = blockIdx.x;
    const int head = blockIdx.y;
    const int n    = threadIdx.x;

    __shared__ float ks[64][33];
    __shared__ float vs[64][33];
    __shared__ float sp[64][65];
    __shared__ float sbias[225];
    __shared__ int   lab[64];

    const __half* base = qkv + (long)win * NPW * (3 * Cdim);
    const __half* krow = base + n * (3 * Cdim) + Cdim + head * HD;
    const __half* vrow = base + n * (3 * Cdim) + 2 * Cdim + head * HD;
#pragma unroll
    for (int d = 0; d < HD; d++) {
        ks[n][d] = __half2float(krow[d]);
        vs[n][d] = __half2float(vrow[d]);
    }
    for (int idx = n; idx < 225; idx += 64) sbias[idx] = rpb[idx * NH + head];
    {
        const int wi = win & 255;
        const int gh = (wi >> 4) * 8 + (n >> 3);
        const int gw = (wi & 15) * 8 + (n & 7);
        const int rh = (gh < Himg - WS) ? 0 : ((gh < Himg - SHIFT) ? 1 : 2);
        const int rw = (gw < Wimg - WS) ? 0 : ((gw < Wimg - SHIFT) ? 1 : 2);
        lab[n] = rh * 3 + rw;
    }
    __syncthreads();

    float q[HD];
    const __half* qrow = base + n * (3 * Cdim) + head * HD;
#pragma unroll
    for (int d = 0; d < HD; d++) q[d] = __half2float(qrow[d]) * 0.17677669529663687f;

    const int i = n >> 3, j = n & 7;
    const int myl = lab[n];

    float mx = -1e30f;
    for (int m = 0; m < 64; m++) {
        float s = 0.f;
#pragma unroll
        for (int d = 0; d < HD; d++) s += q[d] * ks[m][d];
        s += sbias[(i - (m >> 3) + 7) * 15 + (j - (m & 7) + 7)];
        if (lab[m] != myl) s -= 100.f;
        sp[n][m] = s;
        mx = fmaxf(mx, s);
    }
    float sum = 0.f;
    for (int m = 0; m < 64; m++) {
        const float e = expf(sp[n][m] - mx);
        sp[n][m] = e; sum += e;
    }
    const float inv = 1.f / sum;

    float accv[HD];
#pragma unroll
    for (int d = 0; d < HD; d++) accv[d] = 0.f;
    for (int m = 0; m < 64; m++) {
        const float p = sp[n][m];
#pragma unroll
        for (int d = 0; d < HD; d++) accv[d] += p * vs[m][d];
    }
    __half* dst = out + ((long)win * NPW + n) * Cdim + head * HD;
#pragma unroll
    for (int d = 0; d < HD; d++) dst[d] = __float2half_rn(accv[d] * inv);
}

// ---------------------------------------------------------------------------
// window reverse + unshift + residual + LN2 (one warp / token)
// x1 fp32 exact, ln2 half
// ---------------------------------------------------------------------------
__global__ void unshift_add_ln2_kernel(const float* __restrict__ x,
                                       const float* __restrict__ proj,
                                       const float* __restrict__ g2,
                                       const float* __restrict__ b2,
                                       float* __restrict__ x1,
                                       __half* __restrict__ ln2)
{
    const int warp = threadIdx.x >> 5;
    const int lane = threadIdx.x & 31;
    const long t = (long)blockIdx.x * 8 + warp;
    const int b  = (int)(t >> 14);
    const int hw = (int)(t & 16383);
    const int h  = hw >> 7, w = hw & 127;
    const int sh = (h + 128 - SHIFT) & 127;
    const int sw = (w + 128 - SHIFT) & 127;
    const long wt = (((long)b * 256 + (sh >> 3) * 16 + (sw >> 3)) * 64 + (sh & 7) * 8 + (sw & 7));

    const float* xs = x    + t  * Cdim;
    const float* ps = proj + wt * Cdim;

    float v[6];
    float s = 0.f, ss = 0.f;
#pragma unroll
    for (int i = 0; i < 6; i++) {
        const int c = lane + 32 * i;
        v[i] = xs[c] + ps[c];
        s += v[i]; ss += v[i] * v[i];
    }
    float* x1p = x1 + t * Cdim;
#pragma unroll
    for (int i = 0; i < 6; i++) x1p[lane + 32 * i] = v[i];
#pragma unroll
    for (int o = 16; o > 0; o >>= 1) {
        s  += __shfl_xor_sync(0xffffffffu, s,  o);
        ss += __shfl_xor_sync(0xffffffffu, ss, o);
    }
    const float mu  = s * (1.f / Cdim);
    const float var = ss * (1.f / Cdim) - mu * mu;
    const float r   = rsqrtf(var + 1e-5f);
    __half* lp = ln2 + t * Cdim;
#pragma unroll
    for (int i = 0; i < 6; i++) {
        const int c = lane + 32 * i;
        lp[c] = __float2half_rn((v[i] - mu) * r * g2[c] + b2[c]);
    }
}

// ---------------------------------------------------------------------------
// Launch
// ---------------------------------------------------------------------------
extern "C" void kernel_launch(void* const* d_in, const int* in_sizes, int n_in,
                              void* d_out, int out_size)
{
    const float* x      = (const float*)d_in[0];
    const float* g1     = (const float*)d_in[1];
    const float* b1     = (const float*)d_in[2];
    const float* qkv_w  = (const float*)d_in[3];
    const float* qkv_b  = (const float*)d_in[4];
    const float* rpb    = (const float*)d_in[5];
    const float* proj_w = (const float*)d_in[6];
    const float* proj_b = (const float*)d_in[7];
    const float* g2     = (const float*)d_in[8];
    const float* b2     = (const float*)d_in[9];
    const float* fc1_w  = (const float*)d_in[10];
    const float* fc1_b  = (const float*)d_in[11];
    const float* fc2_w  = (const float*)d_in[12];
    const float* fc2_b  = (const float*)d_in[13];
    float* out = (float*)d_out;

    __half *p_win, *p_qkv, *p_att, *p_ln2, *p_hh, *p_wh;
    float *p_x1, *p_proj;
    cudaGetSymbolAddress((void**)&p_win, g_win);
    cudaGetSymbolAddress((void**)&p_qkv, g_qkv);
    cudaGetSymbolAddress((void**)&p_att, g_att);
    cudaGetSymbolAddress((void**)&p_ln2, g_ln2);
    cudaGetSymbolAddress((void**)&p_hh,  g_hh);
    cudaGetSymbolAddress((void**)&p_x1,  g_x1);
    cudaGetSymbolAddress((void**)&p_proj, g_proj);
    cudaGetSymbolAddress((void**)&p_wh,  g_wh);

    static bool attr_set = false;
    if (!attr_set) {
        cudaFuncSetAttribute(gemm_h<0,1>, cudaFuncAttributeMaxDynamicSharedMemorySize, GEMM_SMEM);
        cudaFuncSetAttribute(gemm_h<0,0>, cudaFuncAttributeMaxDynamicSharedMemorySize, GEMM_SMEM);
        cudaFuncSetAttribute(gemm_h<1,1>, cudaFuncAttributeMaxDynamicSharedMemorySize, GEMM_SMEM);
        cudaFuncSetAttribute(gemm_h<2,0>, cudaFuncAttributeMaxDynamicSharedMemorySize, GEMM_SMEM);
        attr_set = true;
    }

    __half* w_qkv = p_wh;
    __half* w_prj = p_wh + 110592;
    __half* w_fc1 = p_wh + 147456;
    __half* w_fc2 = p_wh + 294912;

    // 0. weights fp32 -> fp16
    tohalf_kernel<<<(110592 + 1023) / 1024, 256>>>(qkv_w,  w_qkv, 110592);
    tohalf_kernel<<<( 36864 + 1023) / 1024, 256>>>(proj_w, w_prj,  36864);
    tohalf_kernel<<<(147456 + 1023) / 1024, 256>>>(fc1_w,  w_fc1, 147456);
    tohalf_kernel<<<(147456 + 1023) / 1024, 256>>>(fc2_w,  w_fc2, 147456);

    const int M = NTOK;  // 131072

    // 1. LN1 + shift + window -> half
    ln1_window_kernel<<<M / 8, 256>>>(x, g1, b1, p_win);

    // 2. QKV: [M,576] half
    gemm_h<0,1><<<dim3(M / 128, 3), 256, GEMM_SMEM>>>(
        p_win, w_qkv, qkv_b, nullptr, p_qkv, 3 * Cdim, Cdim);

    // 3. Window attention -> half
    attn_kernel<<<dim3(NWIN, NH), 64>>>(p_qkv, rpb, p_att);

    // 4. proj: [M,192] fp32
    gemm_h<0,0><<<dim3(M / 128, 1), 256, GEMM_SMEM>>>(
        p_att, w_prj, proj_b, nullptr, p_proj, Cdim, Cdim);

    // 5. unshift + residual + LN2
    unshift_add_ln2_kernel<<<M / 8, 256>>>(x, p_proj, g2, b2, p_x1, p_ln2);

    // 6. FC1 + GELU: [M,768] half
    gemm_h<1,1><<<dim3(M / 128, 4), 256, GEMM_SMEM>>>(
        p_ln2, w_fc1, fc1_b, nullptr, p_hh, HID, Cdim);

    // 7. FC2 + residual: out fp32
    gemm_h<2,0><<<dim3(M / 128, 1), 256, GEMM_SMEM>>>(
        p_hh, w_fc2, fc2_b, p_x1, out, Cdim, HID);
}

// round 5
// speedup vs baseline: 4.0120x; 1.3764x over previous
#include <cuda_runtime.h>
#include <cuda_fp16.h>
#include <math.h>
#include <stdint.h>

// ---------------------------------------------------------------------------
// Problem constants
// ---------------------------------------------------------------------------
#define Bsz   8
#define Himg  128
#define Wimg  128
#define Cdim  192
#define HID   768
#define WS    8
#define SHIFT 4
#define NH    6
#define HD    32
#define NTOK  (Bsz*Himg*Wimg)             // 131072
#define NWIN  2048
#define NPW   64

// ---------------------------------------------------------------------------
// Scratch
// ---------------------------------------------------------------------------
__device__ __align__(16) __half g_qkv[(size_t)NTOK * 3 * Cdim];
__device__ __align__(16) __half g_att[(size_t)NTOK * Cdim];
__device__ __align__(16) __half g_hh [(size_t)NTOK * HID];
__device__ __align__(16) float  g_x1 [(size_t)NTOK * Cdim];
__device__ __align__(16) __half g_wh[442368];   // qkv@0 proj@110592 fc1@147456 fc2@294912

// ---------------------------------------------------------------------------
// Helpers
// ---------------------------------------------------------------------------
__device__ __forceinline__ uint32_t smem_u32(const void* p) {
    uint32_t a;
    asm("{ .reg .u64 t; cvta.to.shared.u64 t, %1; cvt.u32.u64 %0, t; }" : "=r"(a) : "l"(p));
    return a;
}
__device__ __forceinline__ void cp_async16(uint32_t dst, const void* src) {
    asm volatile("cp.async.cg.shared.global [%0], [%1], 16;" :: "r"(dst), "l"(src) : "memory");
}
__device__ __forceinline__ uint32_t lds32(uint32_t addr) {
    uint32_t v;
    asm volatile("ld.shared.b32 %0, [%1];" : "=r"(v) : "r"(addr));
    return v;
}
__device__ __forceinline__ void sts32(uint32_t addr, uint32_t v) {
    asm volatile("st.shared.b32 [%0], %1;" :: "r"(addr), "r"(v) : "memory");
}
__device__ __forceinline__ void mma16(float* c, const uint32_t* a, const uint32_t* b) {
    asm volatile("mma.sync.aligned.m16n8k16.row.col.f32.f16.f16.f32 "
        "{%0,%1,%2,%3}, {%4,%5,%6,%7}, {%8,%9}, {%0,%1,%2,%3};"
        : "+f"(c[0]), "+f"(c[1]), "+f"(c[2]), "+f"(c[3])
        : "r"(a[0]), "r"(a[1]), "r"(a[2]), "r"(a[3]), "r"(b[0]), "r"(b[1]));
}
// window-layout token -> original-layout token (unshift)
__device__ __forceinline__ long win2orig(long t) {
    const int b_ = (int)(t >> 6), n = (int)(t & 63);
    const int b = b_ >> 8, wi = b_ & 255;
    const int h = ((wi >> 4) * 8 + (n >> 3) + SHIFT) & 127;
    const int w = ((wi & 15) * 8 + (n & 7) + SHIFT) & 127;
    return ((long)b * 128 + h) * 128 + w;
}

#define ACHUNK 16384   // 128 rows x 64 halves (128B/row)
#define BCHUNK 24576   // 192 rows x 64 halves

// ---------------------------------------------------------------------------
// Fused LN + GEMM: C[M,N] = LN(A)[M,192] @ B[N,192]^T + bias (+GELU)
// A fp32 (MAP=1: shift/window gather; MAP=0: identity). Output half.
// A resident (3 chunks), B streamed double-buffered per (n-tile, chunk).
// ---------------------------------------------------------------------------
#define LN_SMEM (3*ACHUNK + 2*BCHUNK + 128)

template <int MAP, int EPI>
__global__ void __launch_bounds__(256, 1)
gemm_ln(const float* __restrict__ Asrc, const __half* __restrict__ B,
        const float* __restrict__ bias, const float* __restrict__ gamma,
        const float* __restrict__ beta, __half* __restrict__ C, int N)
{
    extern __shared__ char dsm[];
    const uint32_t base  = (smem_u32(dsm) + 127u) & ~127u;
    const uint32_t bBase = base + 3 * ACHUNK;

    const int tid  = threadIdx.x;
    const int wid  = tid >> 5;
    const int lane = tid & 31;
    const int g    = lane >> 2;
    const int tig  = lane & 3;
    const int m0w  = (wid >> 2) * 64;
    const int n0w  = (wid & 3) * 48;
    const long m0  = (long)blockIdx.x * 128;

    const int lm = tid >> 3;      // 0..31
    const int lq = tid & 7;
    const uint32_t bswz = (uint32_t)((lq ^ (lm & 7)) << 4);
    const int NT = N / 192;

    // B chunk issue: buffer buf, n-tile nt, k-chunk c
#define ISSUE_B(buf, nt, c) do { \
        const uint32_t bd = bBase + (uint32_t)(buf) * BCHUNK + (uint32_t)lm * 128 + bswz; \
        const __half* sb = B + ((long)(nt) * 192 + lm) * Cdim + (c) * 64 + lq * 8; \
        _Pragma("unroll") \
        for (int it = 0; it < 6; it++) \
            cp_async16(bd + it * 4096, sb + (long)it * 32 * Cdim); \
        asm volatile("cp.async.commit_group;" ::: "memory"); \
    } while (0)

    ISSUE_B(0, 0, 0);

    // ---- Phase 1: LN of A (each warp: 16 rows) ----
#pragma unroll 1
    for (int rr = 0; rr < 16; rr++) {
        const int row = wid * 16 + rr;
        const long t = m0 + row;
        const float* src = Asrc + (MAP ? win2orig(t) : t) * Cdim;
        float2 v[3];
        float s = 0.f, ss = 0.f;
#pragma unroll
        for (int i = 0; i < 3; i++) {
            v[i] = *(const float2*)(src + 2 * lane + 64 * i);
            s  += v[i].x + v[i].y;
            ss += v[i].x * v[i].x + v[i].y * v[i].y;
        }
#pragma unroll
        for (int o = 16; o > 0; o >>= 1) {
            s  += __shfl_xor_sync(0xffffffffu, s,  o);
            ss += __shfl_xor_sync(0xffffffffu, ss, o);
        }
        const float mu  = s * (1.f / Cdim);
        const float var = ss * (1.f / Cdim) - mu * mu;
        const float r   = rsqrtf(var + 1e-5f);
        const uint32_t rowaddr = base + (uint32_t)row * 128 +
            ((((uint32_t)lane >> 2) ^ ((uint32_t)row & 7)) << 4) + ((uint32_t)lane & 3) * 4;
#pragma unroll
        for (int i = 0; i < 3; i++) {
            const int c = 2 * lane + 64 * i;
            const float2 gm = *(const float2*)(gamma + c);
            const float2 bt = *(const float2*)(beta + c);
            const float a0 = (v[i].x - mu) * r * gm.x + bt.x;
            const float a1 = (v[i].y - mu) * r * gm.y + bt.y;
            const __half2 hv = __floats2half2_rn(a0, a1);
            sts32(rowaddr + (uint32_t)i * ACHUNK, *(const uint32_t*)&hv);
        }
    }

    // ---- Phase 2: GEMM over n-tiles ----
    const uint32_t aRowOff = (uint32_t)(m0w + g) * 128 + (uint32_t)tig * 4;
    const uint32_t bRowOff = (uint32_t)(n0w + g) * 128 + (uint32_t)tig * 4;

    float acc[4][6][4];
#pragma unroll
    for (int mi = 0; mi < 4; mi++)
#pragma unroll
        for (int ni = 0; ni < 6; ni++)
#pragma unroll
            for (int c = 0; c < 4; c++) acc[mi][ni][c] = 0.f;

    const int total = NT * 3;
    for (int ci = 0; ci < total; ci++) {
        const int c = ci % 3;
        if (ci + 1 < total) {
            const int cn = ci + 1;
            ISSUE_B(cn & 1, cn / 3, cn % 3);
            asm volatile("cp.async.wait_group 1;" ::: "memory");
        } else {
            asm volatile("cp.async.wait_group 0;" ::: "memory");
        }
        __syncthreads();

        const uint32_t aRow = base + (uint32_t)c * ACHUNK + aRowOff;
        const uint32_t bRow = bBase + (uint32_t)(ci & 1) * BCHUNK + bRowOff;

#pragma unroll
        for (int s = 0; s < 4; s++) {
            const uint32_t koff0 = (uint32_t)(((2 * s) ^ g) << 4);
            const uint32_t koff1 = koff0 ^ 16u;
            uint32_t af[4][4];
#pragma unroll
            for (int mi = 0; mi < 4; mi++) {
                const uint32_t p = aRow + mi * 2048;
                af[mi][0] = lds32(p + koff0);
                af[mi][1] = lds32(p + 1024 + koff0);
                af[mi][2] = lds32(p + koff1);
                af[mi][3] = lds32(p + 1024 + koff1);
            }
            uint32_t bf[6][2];
#pragma unroll
            for (int ni = 0; ni < 6; ni++) {
                const uint32_t p = bRow + ni * 1024;
                bf[ni][0] = lds32(p + koff0);
                bf[ni][1] = lds32(p + koff1);
            }
#pragma unroll
            for (int mi = 0; mi < 4; mi++)
#pragma unroll
                for (int ni = 0; ni < 6; ni++)
                    mma16(acc[mi][ni], af[mi], bf[ni]);
        }

        if (c == 2) {
            const int nt = ci / 3;
#pragma unroll
            for (int mi = 0; mi < 4; mi++) {
                const long r0 = m0 + m0w + mi * 16 + g;
                const long r1 = r0 + 8;
#pragma unroll
                for (int ni = 0; ni < 6; ni++) {
                    const int col = nt * 192 + n0w + ni * 8 + 2 * tig;
                    const float b0 = bias[col], b1 = bias[col + 1];
                    float v0 = acc[mi][ni][0] + b0;
                    float v1 = acc[mi][ni][1] + b1;
                    float v2 = acc[mi][ni][2] + b0;
                    float v3 = acc[mi][ni][3] + b1;
                    if (EPI == 1) {
                        v0 = 0.5f * v0 * (1.f + erff(v0 * 0.7071067811865475f));
                        v1 = 0.5f * v1 * (1.f + erff(v1 * 0.7071067811865475f));
                        v2 = 0.5f * v2 * (1.f + erff(v2 * 0.7071067811865475f));
                        v3 = 0.5f * v3 * (1.f + erff(v3 * 0.7071067811865475f));
                    }
                    *(__half2*)(C + r0 * N + col) = __floats2half2_rn(v0, v1);
                    *(__half2*)(C + r1 * N + col) = __floats2half2_rn(v2, v3);
                    acc[mi][ni][0] = 0.f; acc[mi][ni][1] = 0.f;
                    acc[mi][ni][2] = 0.f; acc[mi][ni][3] = 0.f;
                }
            }
        }
        __syncthreads();
    }
#undef ISSUE_B
}

// ---------------------------------------------------------------------------
// Streaming fp16 GEMM (A half): proj (EPI=3: unshift + x residual -> x1 fp32)
// and FC2 (EPI=2: +res fp32 -> out fp32).
// ---------------------------------------------------------------------------
#define ASTAGE 16384
#define BSTAGE 24576
#define STAGE  (ASTAGE + BSTAGE)
#define GEMM_SMEM (2*STAGE + 128)

template <int EPI>
__global__ void __launch_bounds__(256, 1)
gemm_h(const __half* __restrict__ A, const __half* __restrict__ B,
       const float* __restrict__ bias, const float* __restrict__ res,
       float* __restrict__ C, int N, int K)
{
    extern __shared__ char dsm[];
    const uint32_t base = (smem_u32(dsm) + 127u) & ~127u;

    const int tid  = threadIdx.x;
    const int wid  = tid >> 5;
    const int lane = tid & 31;
    const int g    = lane >> 2;
    const int tig  = lane & 3;
    const int m0w  = (wid >> 2) * 64;
    const int n0w  = (wid & 3) * 48;

    const long m0 = (long)blockIdx.x * 128;
    const int  n0 = blockIdx.y * 192;

    const int lm = tid >> 3;
    const int lq = tid & 7;
    const __half* srcA = A + (m0 + lm) * K + lq * 8;
    const __half* srcB = B + (long)(n0 + lm) * K + lq * 8;
    const uint32_t swz = (uint32_t)((lq ^ (lm & 7)) << 4);
    const uint32_t dstA0 = base + (uint32_t)lm * 128 + swz;
    const uint32_t dstB0 = base + ASTAGE + (uint32_t)lm * 128 + swz;

    float acc[4][6][4];
#pragma unroll
    for (int mi = 0; mi < 4; mi++)
#pragma unroll
        for (int ni = 0; ni < 6; ni++)
#pragma unroll
            for (int c = 0; c < 4; c++) acc[mi][ni][c] = 0.f;

    const int NC = K >> 6;

#define ISSUE(buf, kc_) do { \
        const uint32_t so = (uint32_t)(buf) * STAGE; \
        const __half* sa = srcA + (kc_); \
        const __half* sb = srcB + (kc_); \
        _Pragma("unroll") \
        for (int it = 0; it < 4; it++) \
            cp_async16(dstA0 + so + it * 4096, sa + (long)it * 32 * K); \
        _Pragma("unroll") \
        for (int it = 0; it < 6; it++) \
            cp_async16(dstB0 + so + it * 4096, sb + (long)it * 32 * K); \
        asm volatile("cp.async.commit_group;" ::: "memory"); \
    } while (0)

    ISSUE(0, 0);

    const uint32_t aRow0 = base + (uint32_t)(m0w + g) * 128 + (uint32_t)tig * 4;
    const uint32_t bRow0 = base + ASTAGE + (uint32_t)(n0w + g) * 128 + (uint32_t)tig * 4;

    for (int i = 0; i < NC; i++) {
        if (i + 1 < NC) {
            ISSUE((i + 1) & 1, (i + 1) << 6);
            asm volatile("cp.async.wait_group 1;" ::: "memory");
        } else {
            asm volatile("cp.async.wait_group 0;" ::: "memory");
        }
        __syncthreads();

        const uint32_t so = (uint32_t)(i & 1) * STAGE;
        const uint32_t aRow = aRow0 + so;
        const uint32_t bRow = bRow0 + so;

#pragma unroll
        for (int s = 0; s < 4; s++) {
            const uint32_t koff0 = (uint32_t)(((2 * s) ^ g) << 4);
            const uint32_t koff1 = koff0 ^ 16u;
            uint32_t af[4][4];
#pragma unroll
            for (int mi = 0; mi < 4; mi++) {
                const uint32_t p = aRow + mi * 2048;
                af[mi][0] = lds32(p + koff0);
                af[mi][1] = lds32(p + 1024 + koff0);
                af[mi][2] = lds32(p + koff1);
                af[mi][3] = lds32(p + 1024 + koff1);
            }
            uint32_t bf[6][2];
#pragma unroll
            for (int ni = 0; ni < 6; ni++) {
                const uint32_t p = bRow + ni * 1024;
                bf[ni][0] = lds32(p + koff0);
                bf[ni][1] = lds32(p + koff1);
            }
#pragma unroll
            for (int mi = 0; mi < 4; mi++)
#pragma unroll
                for (int ni = 0; ni < 6; ni++)
                    mma16(acc[mi][ni], af[mi], bf[ni]);
        }
        __syncthreads();
    }
#undef ISSUE

#pragma unroll
    for (int mi = 0; mi < 4; mi++) {
        const long rw0 = m0 + m0w + mi * 16 + g;
        const long rw1 = rw0 + 8;
        const long r0 = (EPI == 3) ? win2orig(rw0) : rw0;
        const long r1 = (EPI == 3) ? win2orig(rw1) : rw1;
#pragma unroll
        for (int ni = 0; ni < 6; ni++) {
            const int col = n0 + n0w + ni * 8 + 2 * tig;
            const float b0 = bias[col], b1 = bias[col + 1];
            float v0 = acc[mi][ni][0] + b0;
            float v1 = acc[mi][ni][1] + b1;
            float v2 = acc[mi][ni][2] + b0;
            float v3 = acc[mi][ni][3] + b1;
            {
                const float2 ra = *(const float2*)(res + r0 * N + col);
                const float2 rb = *(const float2*)(res + r1 * N + col);
                v0 += ra.x; v1 += ra.y; v2 += rb.x; v3 += rb.y;
            }
            *(float2*)(C + r0 * N + col) = make_float2(v0, v1);
            *(float2*)(C + r1 * N + col) = make_float2(v2, v3);
        }
    }
}

// ---------------------------------------------------------------------------
// Weight fp32 -> fp16
// ---------------------------------------------------------------------------
__global__ void tohalf_kernel(const float* __restrict__ src, __half* __restrict__ dst, int n)
{
    const int i = blockIdx.x * 1024 + threadIdx.x * 4;
    if (i + 3 < n) {
        float4 v = *(const float4*)(src + i);
        __half2* d = (__half2*)(dst + i);
        d[0] = __floats2half2_rn(v.x, v.y);
        d[1] = __floats2half2_rn(v.z, v.w);
    } else {
        for (int j = i; j < n; j++) dst[j] = __float2half_rn(src[j]);
    }
}

// ---------------------------------------------------------------------------
// Fused window attention. Block per (window, head), 64 threads.
// float4 broadcast reads of K/V from padded smem.
// ---------------------------------------------------------------------------
__global__ void __launch_bounds__(64)
attn_kernel(const __half* __restrict__ qkv,
            const float* __restrict__ rpb,
            __half* __restrict__ out)
{
    const int win  = blockIdx.x;
    const int head = blockIdx.y;
    const int n    = threadIdx.x;

    __shared__ float ks[64][36];
    __shared__ float vs[64][36];
    __shared__ float sp[64][65];
    __shared__ float sbias[225];
    __shared__ int   lab[64];

    const __half* base = qkv + (long)win * NPW * (3 * Cdim);
    const __half2* k2 = (const __half2*)(base + n * (3 * Cdim) + Cdim + head * HD);
    const __half2* v2 = (const __half2*)(base + n * (3 * Cdim) + 2 * Cdim + head * HD);
#pragma unroll
    for (int dp = 0; dp < 16; dp++) {
        const float2 fk = __half22float2(k2[dp]);
        const float2 fv = __half22float2(v2[dp]);
        ks[n][2 * dp] = fk.x; ks[n][2 * dp + 1] = fk.y;
        vs[n][2 * dp] = fv.x; vs[n][2 * dp + 1] = fv.y;
    }
    for (int idx = n; idx < 225; idx += 64) sbias[idx] = rpb[idx * NH + head];
    {
        const int wi = win & 255;
        const int gh = (wi >> 4) * 8 + (n >> 3);
        const int gw = (wi & 15) * 8 + (n & 7);
        const int rh = (gh < Himg - WS) ? 0 : ((gh < Himg - SHIFT) ? 1 : 2);
        const int rw = (gw < Wimg - WS) ? 0 : ((gw < Wimg - SHIFT) ? 1 : 2);
        lab[n] = rh * 3 + rw;
    }
    __syncthreads();

    float q[HD];
    const __half2* q2 = (const __half2*)(base + n * (3 * Cdim) + head * HD);
#pragma unroll
    for (int dp = 0; dp < 16; dp++) {
        const float2 f = __half22float2(q2[dp]);
        q[2 * dp]     = f.x * 0.17677669529663687f;
        q[2 * dp + 1] = f.y * 0.17677669529663687f;
    }

    const int i = n >> 3, j = n & 7;
    const int myl = lab[n];

    float mx = -1e30f;
    for (int m = 0; m < 64; m++) {
        const float4* kr = (const float4*)&ks[m][0];
        float s = 0.f;
#pragma unroll
        for (int t = 0; t < 8; t++) {
            const float4 kv = kr[t];
            s += q[4*t] * kv.x + q[4*t+1] * kv.y + q[4*t+2] * kv.z + q[4*t+3] * kv.w;
        }
        s += sbias[(i - (m >> 3) + 7) * 15 + (j - (m & 7) + 7)];
        if (lab[m] != myl) s -= 100.f;
        sp[n][m] = s;
        mx = fmaxf(mx, s);
    }
    float sum = 0.f;
    for (int m = 0; m < 64; m++) {
        const float e = expf(sp[n][m] - mx);
        sp[n][m] = e; sum += e;
    }
    const float inv = 1.f / sum;

    float accv[HD];
#pragma unroll
    for (int d = 0; d < HD; d++) accv[d] = 0.f;
    for (int m = 0; m < 64; m++) {
        const float p = sp[n][m];
        const float4* vr = (const float4*)&vs[m][0];
#pragma unroll
        for (int t = 0; t < 8; t++) {
            const float4 vv = vr[t];
            accv[4*t]   += p * vv.x;
            accv[4*t+1] += p * vv.y;
            accv[4*t+2] += p * vv.z;
            accv[4*t+3] += p * vv.w;
        }
    }
    __half* dst = out + ((long)win * NPW + n) * Cdim + head * HD;
#pragma unroll
    for (int dp = 0; dp < 16; dp++)
        *(__half2*)(dst + 2 * dp) = __floats2half2_rn(accv[2*dp] * inv, accv[2*dp+1] * inv);
}

// ---------------------------------------------------------------------------
// Launch
// ---------------------------------------------------------------------------
extern "C" void kernel_launch(void* const* d_in, const int* in_sizes, int n_in,
                              void* d_out, int out_size)
{
    const float* x      = (const float*)d_in[0];
    const float* g1     = (const float*)d_in[1];
    const float* b1     = (const float*)d_in[2];
    const float* qkv_w  = (const float*)d_in[3];
    const float* qkv_b  = (const float*)d_in[4];
    const float* rpb    = (const float*)d_in[5];
    const float* proj_w = (const float*)d_in[6];
    const float* proj_b = (const float*)d_in[7];
    const float* g2     = (const float*)d_in[8];
    const float* b2     = (const float*)d_in[9];
    const float* fc1_w  = (const float*)d_in[10];
    const float* fc1_b  = (const float*)d_in[11];
    const float* fc2_w  = (const float*)d_in[12];
    const float* fc2_b  = (const float*)d_in[13];
    float* out = (float*)d_out;

    __half *p_qkv, *p_att, *p_hh, *p_wh;
    float *p_x1;
    cudaGetSymbolAddress((void**)&p_qkv, g_qkv);
    cudaGetSymbolAddress((void**)&p_att, g_att);
    cudaGetSymbolAddress((void**)&p_hh,  g_hh);
    cudaGetSymbolAddress((void**)&p_x1,  g_x1);
    cudaGetSymbolAddress((void**)&p_wh,  g_wh);

    static bool attr_set = false;
    if (!attr_set) {
        cudaFuncSetAttribute(gemm_ln<1,0>, cudaFuncAttributeMaxDynamicSharedMemorySize, LN_SMEM);
        cudaFuncSetAttribute(gemm_ln<0,1>, cudaFuncAttributeMaxDynamicSharedMemorySize, LN_SMEM);
        cudaFuncSetAttribute(gemm_h<3>, cudaFuncAttributeMaxDynamicSharedMemorySize, GEMM_SMEM);
        cudaFuncSetAttribute(gemm_h<2>, cudaFuncAttributeMaxDynamicSharedMemorySize, GEMM_SMEM);
        attr_set = true;
    }

    __half* w_qkv = p_wh;
    __half* w_prj = p_wh + 110592;
    __half* w_fc1 = p_wh + 147456;
    __half* w_fc2 = p_wh + 294912;

    // 0. weights fp32 -> fp16
    tohalf_kernel<<<(110592 + 1023) / 1024, 256>>>(qkv_w,  w_qkv, 110592);
    tohalf_kernel<<<( 36864 + 1023) / 1024, 256>>>(proj_w, w_prj,  36864);
    tohalf_kernel<<<(147456 + 1023) / 1024, 256>>>(fc1_w,  w_fc1, 147456);
    tohalf_kernel<<<(147456 + 1023) / 1024, 256>>>(fc2_w,  w_fc2, 147456);

    const int M = NTOK;  // 131072, 1024 M-tiles

    // 1. QKV with fused LN1 + shift/window gather: qkv[M,576] half
    gemm_ln<1,0><<<M / 128, 256, LN_SMEM>>>(x, w_qkv, qkv_b, g1, b1, p_qkv, 3 * Cdim);

    // 2. Window attention -> att[M,192] half
    attn_kernel<<<dim3(NWIN, NH), 64>>>(p_qkv, rpb, p_att);

    // 3. proj + unshift + residual: x1[M,192] fp32 (original layout)
    gemm_h<3><<<dim3(M / 128, 1), 256, GEMM_SMEM>>>(
        p_att, w_prj, proj_b, x, p_x1, Cdim, Cdim);

    // 4. FC1 with fused LN2 + GELU: hh[M,768] half
    gemm_ln<0,1><<<M / 128, 256, LN_SMEM>>>(p_x1, w_fc1, fc1_b, g2, b2, p_hh, HID);

    // 5. FC2 + residual: out[M,192] fp32
    gemm_h<2><<<dim3(M / 128, 1), 256, GEMM_SMEM>>>(
        p_hh, w_fc2, fc2_b, p_x1, out, Cdim, HID);
}

// round 6
// speedup vs baseline: 4.0874x; 1.0188x over previous
#include <cuda_runtime.h>
#include <cuda_fp16.h>
#include <math.h>
#include <stdint.h>

// ---------------------------------------------------------------------------
// Problem constants
// ---------------------------------------------------------------------------
#define Bsz   8
#define Himg  128
#define Wimg  128
#define Cdim  192
#define HID   768
#define WS    8
#define SHIFT 4
#define NH    6
#define HD    32
#define NTOK  (Bsz*Himg*Wimg)             // 131072
#define NWIN  2048
#define NPW   64

// ---------------------------------------------------------------------------
// Scratch
// ---------------------------------------------------------------------------
__device__ __align__(16) __half g_qkv[(size_t)NTOK * 3 * Cdim];
__device__ __align__(16) __half g_att[(size_t)NTOK * Cdim];
__device__ __align__(16) __half g_ln2[(size_t)NTOK * Cdim];
__device__ __align__(16) __half g_hh [(size_t)NTOK * HID];
__device__ __align__(16) float  g_x1 [(size_t)NTOK * Cdim];
__device__ __align__(16) __half g_wh[442368];   // qkv@0 proj@110592 fc1@147456 fc2@294912

// ---------------------------------------------------------------------------
// Helpers
// ---------------------------------------------------------------------------
__device__ __forceinline__ uint32_t smem_u32(const void* p) {
    uint32_t a;
    asm("{ .reg .u64 t; cvta.to.shared.u64 t, %1; cvt.u32.u64 %0, t; }" : "=r"(a) : "l"(p));
    return a;
}
__device__ __forceinline__ void cp_async16(uint32_t dst, const void* src) {
    asm volatile("cp.async.cg.shared.global [%0], [%1], 16;" :: "r"(dst), "l"(src) : "memory");
}
__device__ __forceinline__ uint32_t lds32(uint32_t addr) {
    uint32_t v;
    asm volatile("ld.shared.b32 %0, [%1];" : "=r"(v) : "r"(addr));
    return v;
}
__device__ __forceinline__ void sts32(uint32_t addr, uint32_t v) {
    asm volatile("st.shared.b32 [%0], %1;" :: "r"(addr), "r"(v) : "memory");
}
__device__ __forceinline__ void mma16(float* c, const uint32_t* a, const uint32_t* b) {
    asm volatile("mma.sync.aligned.m16n8k16.row.col.f32.f16.f16.f32 "
        "{%0,%1,%2,%3}, {%4,%5,%6,%7}, {%8,%9}, {%0,%1,%2,%3};"
        : "+f"(c[0]), "+f"(c[1]), "+f"(c[2]), "+f"(c[3])
        : "r"(a[0]), "r"(a[1]), "r"(a[2]), "r"(a[3]), "r"(b[0]), "r"(b[1]));
}
__device__ __forceinline__ long win2orig(long t) {
    const int b_ = (int)(t >> 6), n = (int)(t & 63);
    const int b = b_ >> 8, wi = b_ & 255;
    const int h = ((wi >> 4) * 8 + (n >> 3) + SHIFT) & 127;
    const int w = ((wi & 15) * 8 + (n & 7) + SHIFT) & 127;
    return ((long)b * 128 + h) * 128 + w;
}

#define ACHUNK 16384   // 128 rows x 64 elems (128B/row as half... chunk is 128B rows)
#define BCHUNK 24576   // 192 rows x 64 halves

// ---------------------------------------------------------------------------
// Fused LN + GEMM (QKV): C[M,N] = LN(gather(A))[M,192] @ B[N,192]^T + bias
// ---------------------------------------------------------------------------
#define LN_SMEM (3*ACHUNK + 2*BCHUNK + 128)

__global__ void __launch_bounds__(256, 1)
gemm_ln(const float* __restrict__ Asrc, const __half* __restrict__ B,
        const float* __restrict__ bias, const float* __restrict__ gamma,
        const float* __restrict__ beta, __half* __restrict__ C, int N)
{
    extern __shared__ char dsm[];
    const uint32_t base  = (smem_u32(dsm) + 127u) & ~127u;
    const uint32_t bBase = base + 3 * ACHUNK;

    const int tid  = threadIdx.x;
    const int wid  = tid >> 5;
    const int lane = tid & 31;
    const int g    = lane >> 2;
    const int tig  = lane & 3;
    const int m0w  = (wid >> 2) * 64;
    const int n0w  = (wid & 3) * 48;
    const long m0  = (long)blockIdx.x * 128;

    const int lm = tid >> 3;
    const int lq = tid & 7;
    const uint32_t bswz = (uint32_t)((lq ^ (lm & 7)) << 4);
    const int NT = N / 192;

#define ISSUE_B(buf, nt, c) do { \
        const uint32_t bd = bBase + (uint32_t)(buf) * BCHUNK + (uint32_t)lm * 128 + bswz; \
        const __half* sb = B + ((long)(nt) * 192 + lm) * Cdim + (c) * 64 + lq * 8; \
        _Pragma("unroll") \
        for (int it = 0; it < 6; it++) \
            cp_async16(bd + it * 4096, sb + (long)it * 32 * Cdim); \
        asm volatile("cp.async.commit_group;" ::: "memory"); \
    } while (0)

    ISSUE_B(0, 0, 0);

    // Phase 1: LN of gathered A
#pragma unroll 1
    for (int rr = 0; rr < 16; rr++) {
        const int row = wid * 16 + rr;
        const long t = m0 + row;
        const float* src = Asrc + win2orig(t) * Cdim;
        float2 v[3];
        float s = 0.f, ss = 0.f;
#pragma unroll
        for (int i = 0; i < 3; i++) {
            v[i] = *(const float2*)(src + 2 * lane + 64 * i);
            s  += v[i].x + v[i].y;
            ss += v[i].x * v[i].x + v[i].y * v[i].y;
        }
#pragma unroll
        for (int o = 16; o > 0; o >>= 1) {
            s  += __shfl_xor_sync(0xffffffffu, s,  o);
            ss += __shfl_xor_sync(0xffffffffu, ss, o);
        }
        const float mu  = s * (1.f / Cdim);
        const float var = ss * (1.f / Cdim) - mu * mu;
        const float r   = rsqrtf(var + 1e-5f);
        const uint32_t rowaddr = base + (uint32_t)row * 128 +
            ((((uint32_t)lane >> 2) ^ ((uint32_t)row & 7)) << 4) + ((uint32_t)lane & 3) * 4;
#pragma unroll
        for (int i = 0; i < 3; i++) {
            const int c = 2 * lane + 64 * i;
            const float2 gm = *(const float2*)(gamma + c);
            const float2 bt = *(const float2*)(beta + c);
            const __half2 hv = __floats2half2_rn((v[i].x - mu) * r * gm.x + bt.x,
                                                 (v[i].y - mu) * r * gm.y + bt.y);
            sts32(rowaddr + (uint32_t)i * ACHUNK, *(const uint32_t*)&hv);
        }
    }

    const uint32_t aRowOff = (uint32_t)(m0w + g) * 128 + (uint32_t)tig * 4;
    const uint32_t bRowOff = (uint32_t)(n0w + g) * 128 + (uint32_t)tig * 4;

    float acc[4][6][4];
#pragma unroll
    for (int mi = 0; mi < 4; mi++)
#pragma unroll
        for (int ni = 0; ni < 6; ni++)
#pragma unroll
            for (int c = 0; c < 4; c++) acc[mi][ni][c] = 0.f;

    const int total = NT * 3;
    for (int ci = 0; ci < total; ci++) {
        const int c = ci % 3;
        if (ci + 1 < total) {
            const int cn = ci + 1;
            ISSUE_B(cn & 1, cn / 3, cn % 3);
            asm volatile("cp.async.wait_group 1;" ::: "memory");
        } else {
            asm volatile("cp.async.wait_group 0;" ::: "memory");
        }
        __syncthreads();

        const uint32_t aRow = base + (uint32_t)c * ACHUNK + aRowOff;
        const uint32_t bRow = bBase + (uint32_t)(ci & 1) * BCHUNK + bRowOff;

#pragma unroll
        for (int s = 0; s < 4; s++) {
            const uint32_t koff0 = (uint32_t)(((2 * s) ^ g) << 4);
            const uint32_t koff1 = koff0 ^ 16u;
            uint32_t af[4][4];
#pragma unroll
            for (int mi = 0; mi < 4; mi++) {
                const uint32_t p = aRow + mi * 2048;
                af[mi][0] = lds32(p + koff0);
                af[mi][1] = lds32(p + 1024 + koff0);
                af[mi][2] = lds32(p + koff1);
                af[mi][3] = lds32(p + 1024 + koff1);
            }
            uint32_t bf[6][2];
#pragma unroll
            for (int ni = 0; ni < 6; ni++) {
                const uint32_t p = bRow + ni * 1024;
                bf[ni][0] = lds32(p + koff0);
                bf[ni][1] = lds32(p + koff1);
            }
#pragma unroll
            for (int mi = 0; mi < 4; mi++)
#pragma unroll
                for (int ni = 0; ni < 6; ni++)
                    mma16(acc[mi][ni], af[mi], bf[ni]);
        }

        if (c == 2) {
            const int nt = ci / 3;
#pragma unroll
            for (int mi = 0; mi < 4; mi++) {
                const long r0 = m0 + m0w + mi * 16 + g;
                const long r1 = r0 + 8;
#pragma unroll
                for (int ni = 0; ni < 6; ni++) {
                    const int col = nt * 192 + n0w + ni * 8 + 2 * tig;
                    const float b0 = bias[col], b1 = bias[col + 1];
                    *(__half2*)(C + r0 * N + col) =
                        __floats2half2_rn(acc[mi][ni][0] + b0, acc[mi][ni][1] + b1);
                    *(__half2*)(C + r1 * N + col) =
                        __floats2half2_rn(acc[mi][ni][2] + b0, acc[mi][ni][3] + b1);
                    acc[mi][ni][0] = 0.f; acc[mi][ni][1] = 0.f;
                    acc[mi][ni][2] = 0.f; acc[mi][ni][3] = 0.f;
                }
            }
        }
        __syncthreads();
    }
#undef ISSUE_B
}

// ---------------------------------------------------------------------------
// A-resident fp16 GEMM (FC1): C = GELU(A[M,192] @ B[N,192]^T + bias), half out
// ---------------------------------------------------------------------------
#define HA_SMEM (3*ACHUNK + 2*BCHUNK + 128)

__global__ void __launch_bounds__(256, 1)
gemm_ha(const __half* __restrict__ A, const __half* __restrict__ B,
        const float* __restrict__ bias, __half* __restrict__ C, int N)
{
    extern __shared__ char dsm[];
    const uint32_t base  = (smem_u32(dsm) + 127u) & ~127u;
    const uint32_t bBase = base + 3 * ACHUNK;

    const int tid  = threadIdx.x;
    const int wid  = tid >> 5;
    const int lane = tid & 31;
    const int g    = lane >> 2;
    const int tig  = lane & 3;
    const int m0w  = (wid >> 2) * 64;
    const int n0w  = (wid & 3) * 48;
    const long m0  = (long)blockIdx.x * 128;

    const int lm = tid >> 3;
    const int lq = tid & 7;
    const uint32_t swz = (uint32_t)((lq ^ (lm & 7)) << 4);
    const int NT = N / 192;

    // A: 3 chunks resident (group 0)
    {
        const uint32_t da = base + (uint32_t)lm * 128 + swz;
        const __half* sa = A + (m0 + lm) * Cdim + lq * 8;
#pragma unroll
        for (int c = 0; c < 3; c++)
#pragma unroll
            for (int it = 0; it < 4; it++)
                cp_async16(da + (uint32_t)c * ACHUNK + it * 4096,
                           sa + (long)it * 32 * Cdim + c * 64);
        asm volatile("cp.async.commit_group;" ::: "memory");
    }

#define ISSUE_B(buf, nt, c) do { \
        const uint32_t bd = bBase + (uint32_t)(buf) * BCHUNK + (uint32_t)lm * 128 + swz; \
        const __half* sb = B + ((long)(nt) * 192 + lm) * Cdim + (c) * 64 + lq * 8; \
        _Pragma("unroll") \
        for (int it = 0; it < 6; it++) \
            cp_async16(bd + it * 4096, sb + (long)it * 32 * Cdim); \
        asm volatile("cp.async.commit_group;" ::: "memory"); \
    } while (0)

    ISSUE_B(0, 0, 0);

    const uint32_t aRowOff = (uint32_t)(m0w + g) * 128 + (uint32_t)tig * 4;
    const uint32_t bRowOff = (uint32_t)(n0w + g) * 128 + (uint32_t)tig * 4;

    float acc[4][6][4];
#pragma unroll
    for (int mi = 0; mi < 4; mi++)
#pragma unroll
        for (int ni = 0; ni < 6; ni++)
#pragma unroll
            for (int c = 0; c < 4; c++) acc[mi][ni][c] = 0.f;

    const int total = NT * 3;
    for (int ci = 0; ci < total; ci++) {
        const int c = ci % 3;
        if (ci + 1 < total) {
            const int cn = ci + 1;
            ISSUE_B(cn & 1, cn / 3, cn % 3);
            asm volatile("cp.async.wait_group 1;" ::: "memory");
        } else {
            asm volatile("cp.async.wait_group 0;" ::: "memory");
        }
        __syncthreads();

        const uint32_t aRow = base + (uint32_t)c * ACHUNK + aRowOff;
        const uint32_t bRow = bBase + (uint32_t)(ci & 1) * BCHUNK + bRowOff;

#pragma unroll
        for (int s = 0; s < 4; s++) {
            const uint32_t koff0 = (uint32_t)(((2 * s) ^ g) << 4);
            const uint32_t koff1 = koff0 ^ 16u;
            uint32_t af[4][4];
#pragma unroll
            for (int mi = 0; mi < 4; mi++) {
                const uint32_t p = aRow + mi * 2048;
                af[mi][0] = lds32(p + koff0);
                af[mi][1] = lds32(p + 1024 + koff0);
                af[mi][2] = lds32(p + koff1);
                af[mi][3] = lds32(p + 1024 + koff1);
            }
            uint32_t bf[6][2];
#pragma unroll
            for (int ni = 0; ni < 6; ni++) {
                const uint32_t p = bRow + ni * 1024;
                bf[ni][0] = lds32(p + koff0);
                bf[ni][1] = lds32(p + koff1);
            }
#pragma unroll
            for (int mi = 0; mi < 4; mi++)
#pragma unroll
                for (int ni = 0; ni < 6; ni++)
                    mma16(acc[mi][ni], af[mi], bf[ni]);
        }

        if (c == 2) {
            const int nt = ci / 3;
#pragma unroll
            for (int mi = 0; mi < 4; mi++) {
                const long r0 = m0 + m0w + mi * 16 + g;
                const long r1 = r0 + 8;
#pragma unroll
                for (int ni = 0; ni < 6; ni++) {
                    const int col = nt * 192 + n0w + ni * 8 + 2 * tig;
                    const float b0 = bias[col], b1 = bias[col + 1];
                    float v0 = acc[mi][ni][0] + b0;
                    float v1 = acc[mi][ni][1] + b1;
                    float v2 = acc[mi][ni][2] + b0;
                    float v3 = acc[mi][ni][3] + b1;
                    v0 = 0.5f * v0 * (1.f + erff(v0 * 0.7071067811865475f));
                    v1 = 0.5f * v1 * (1.f + erff(v1 * 0.7071067811865475f));
                    v2 = 0.5f * v2 * (1.f + erff(v2 * 0.7071067811865475f));
                    v3 = 0.5f * v3 * (1.f + erff(v3 * 0.7071067811865475f));
                    *(__half2*)(C + r0 * N + col) = __floats2half2_rn(v0, v1);
                    *(__half2*)(C + r1 * N + col) = __floats2half2_rn(v2, v3);
                    acc[mi][ni][0] = 0.f; acc[mi][ni][1] = 0.f;
                    acc[mi][ni][2] = 0.f; acc[mi][ni][3] = 0.f;
                }
            }
        }
        __syncthreads();
    }
#undef ISSUE_B
}

// ---------------------------------------------------------------------------
// Streaming fp16 GEMM.
// EPI=2: FC2 (+res fp32 -> out fp32)
// EPI=3: proj (unshift + x residual -> x1 fp32, LN2 -> ln2 half)
// ---------------------------------------------------------------------------
#define ASTAGE 16384
#define BSTAGE 24576
#define STAGE  (ASTAGE + BSTAGE)
#define GEMM_SMEM (2*STAGE + 128)

template <int EPI>
__global__ void __launch_bounds__(256, 1)
gemm_h(const __half* __restrict__ A, const __half* __restrict__ B,
       const float* __restrict__ bias, const float* __restrict__ res,
       float* __restrict__ C, __half* __restrict__ C2,
       const float* __restrict__ gamma, const float* __restrict__ beta,
       int N, int K)
{
    extern __shared__ char dsm[];
    const uint32_t base = (smem_u32(dsm) + 127u) & ~127u;

    const int tid  = threadIdx.x;
    const int wid  = tid >> 5;
    const int lane = tid & 31;
    const int g    = lane >> 2;
    const int tig  = lane & 3;
    const int m0w  = (wid >> 2) * 64;
    const int n0w  = (wid & 3) * 48;

    const long m0 = (long)blockIdx.x * 128;
    const int  n0 = blockIdx.y * 192;

    const int lm = tid >> 3;
    const int lq = tid & 7;
    const __half* srcA = A + (m0 + lm) * K + lq * 8;
    const __half* srcB = B + (long)(n0 + lm) * K + lq * 8;
    const uint32_t swz = (uint32_t)((lq ^ (lm & 7)) << 4);
    const uint32_t dstA0 = base + (uint32_t)lm * 128 + swz;
    const uint32_t dstB0 = base + ASTAGE + (uint32_t)lm * 128 + swz;

    float acc[4][6][4];
#pragma unroll
    for (int mi = 0; mi < 4; mi++)
#pragma unroll
        for (int ni = 0; ni < 6; ni++)
#pragma unroll
            for (int c = 0; c < 4; c++) acc[mi][ni][c] = 0.f;

    const int NC = K >> 6;

#define ISSUE(buf, kc_) do { \
        const uint32_t so = (uint32_t)(buf) * STAGE; \
        const __half* sa = srcA + (kc_); \
        const __half* sb = srcB + (kc_); \
        _Pragma("unroll") \
        for (int it = 0; it < 4; it++) \
            cp_async16(dstA0 + so + it * 4096, sa + (long)it * 32 * K); \
        _Pragma("unroll") \
        for (int it = 0; it < 6; it++) \
            cp_async16(dstB0 + so + it * 4096, sb + (long)it * 32 * K); \
        asm volatile("cp.async.commit_group;" ::: "memory"); \
    } while (0)

    ISSUE(0, 0);

    const uint32_t aRow0 = base + (uint32_t)(m0w + g) * 128 + (uint32_t)tig * 4;
    const uint32_t bRow0 = base + ASTAGE + (uint32_t)(n0w + g) * 128 + (uint32_t)tig * 4;

    for (int i = 0; i < NC; i++) {
        if (i + 1 < NC) {
            ISSUE((i + 1) & 1, (i + 1) << 6);
            asm volatile("cp.async.wait_group 1;" ::: "memory");
        } else {
            asm volatile("cp.async.wait_group 0;" ::: "memory");
        }
        __syncthreads();

        const uint32_t so = (uint32_t)(i & 1) * STAGE;
        const uint32_t aRow = aRow0 + so;
        const uint32_t bRow = bRow0 + so;

#pragma unroll
        for (int s = 0; s < 4; s++) {
            const uint32_t koff0 = (uint32_t)(((2 * s) ^ g) << 4);
            const uint32_t koff1 = koff0 ^ 16u;
            uint32_t af[4][4];
#pragma unroll
            for (int mi = 0; mi < 4; mi++) {
                const uint32_t p = aRow + mi * 2048;
                af[mi][0] = lds32(p + koff0);
                af[mi][1] = lds32(p + 1024 + koff0);
                af[mi][2] = lds32(p + koff1);
                af[mi][3] = lds32(p + 1024 + koff1);
            }
            uint32_t bf[6][2];
#pragma unroll
            for (int ni = 0; ni < 6; ni++) {
                const uint32_t p = bRow + ni * 1024;
                bf[ni][0] = lds32(p + koff0);
                bf[ni][1] = lds32(p + koff1);
            }
#pragma unroll
            for (int mi = 0; mi < 4; mi++)
#pragma unroll
                for (int ni = 0; ni < 6; ni++)
                    mma16(acc[mi][ni], af[mi], bf[ni]);
        }
        __syncthreads();
    }
#undef ISSUE

    // add bias + residual into acc (v = x1 values for EPI=3)
#pragma unroll
    for (int mi = 0; mi < 4; mi++) {
        const long rw0 = m0 + m0w + mi * 16 + g;
        const long rw1 = rw0 + 8;
        const long r0 = (EPI == 3) ? win2orig(rw0) : rw0;
        const long r1 = (EPI == 3) ? win2orig(rw1) : rw1;
#pragma unroll
        for (int ni = 0; ni < 6; ni++) {
            const int col = n0 + n0w + ni * 8 + 2 * tig;
            const float b0 = bias[col], b1 = bias[col + 1];
            const float2 ra = *(const float2*)(res + r0 * N + col);
            const float2 rb = *(const float2*)(res + r1 * N + col);
            acc[mi][ni][0] += b0 + ra.x;
            acc[mi][ni][1] += b1 + ra.y;
            acc[mi][ni][2] += b0 + rb.x;
            acc[mi][ni][3] += b1 + rb.y;
        }
    }

    if (EPI == 3) {
        // row stats across warps via smem atomics (reuse staging smem)
        float* rsum   = (float*)(dsm);
        float* rsumsq = rsum + 128;
        if (tid < 128) { rsum[tid] = 0.f; rsumsq[tid] = 0.f; }
        __syncthreads();
#pragma unroll
        for (int mi = 0; mi < 4; mi++) {
            const int row0 = m0w + mi * 16 + g;
            float s0 = 0.f, q0 = 0.f, s1 = 0.f, q1 = 0.f;
#pragma unroll
            for (int ni = 0; ni < 6; ni++) {
                s0 += acc[mi][ni][0] + acc[mi][ni][1];
                q0 += acc[mi][ni][0] * acc[mi][ni][0] + acc[mi][ni][1] * acc[mi][ni][1];
                s1 += acc[mi][ni][2] + acc[mi][ni][3];
                q1 += acc[mi][ni][2] * acc[mi][ni][2] + acc[mi][ni][3] * acc[mi][ni][3];
            }
            atomicAdd(&rsum[row0], s0);   atomicAdd(&rsumsq[row0], q0);
            atomicAdd(&rsum[row0 + 8], s1); atomicAdd(&rsumsq[row0 + 8], q1);
        }
        __syncthreads();
    }

#pragma unroll
    for (int mi = 0; mi < 4; mi++) {
        const long rw0 = m0 + m0w + mi * 16 + g;
        const long rw1 = rw0 + 8;
        const long r0 = (EPI == 3) ? win2orig(rw0) : rw0;
        const long r1 = (EPI == 3) ? win2orig(rw1) : rw1;

        float mu0 = 0.f, rs0 = 0.f, mu1 = 0.f, rs1 = 0.f;
        if (EPI == 3) {
            const float* rsum   = (const float*)(dsm);
            const float* rsumsq = rsum + 128;
            const int row0 = m0w + mi * 16 + g;
            mu0 = rsum[row0] * (1.f / Cdim);
            rs0 = rsqrtf(rsumsq[row0] * (1.f / Cdim) - mu0 * mu0 + 1e-5f);
            mu1 = rsum[row0 + 8] * (1.f / Cdim);
            rs1 = rsqrtf(rsumsq[row0 + 8] * (1.f / Cdim) - mu1 * mu1 + 1e-5f);
        }
#pragma unroll
        for (int ni = 0; ni < 6; ni++) {
            const int col = n0 + n0w + ni * 8 + 2 * tig;
            const float v0 = acc[mi][ni][0], v1 = acc[mi][ni][1];
            const float v2 = acc[mi][ni][2], v3 = acc[mi][ni][3];
            *(float2*)(C + r0 * N + col) = make_float2(v0, v1);
            *(float2*)(C + r1 * N + col) = make_float2(v2, v3);
            if (EPI == 3) {
                const float2 gm = *(const float2*)(gamma + col);
                const float2 bt = *(const float2*)(beta + col);
                *(__half2*)(C2 + r0 * N + col) = __floats2half2_rn(
                    (v0 - mu0) * rs0 * gm.x + bt.x, (v1 - mu0) * rs0 * gm.y + bt.y);
                *(__half2*)(C2 + r1 * N + col) = __floats2half2_rn(
                    (v2 - mu1) * rs1 * gm.x + bt.x, (v3 - mu1) * rs1 * gm.y + bt.y);
            }
        }
    }
}

// ---------------------------------------------------------------------------
// One-shot weight conversion fp32 -> fp16 (4 tensors)
// ---------------------------------------------------------------------------
__global__ void tohalf_all(const float* __restrict__ s0, const float* __restrict__ s1,
                           const float* __restrict__ s2, const float* __restrict__ s3,
                           __half* __restrict__ dst)
{
    const int i = blockIdx.x * 1024 + threadIdx.x * 4;   // element index (mult of 4)
    const float* src;
    int off;
    if (i < 110592)      { src = s0; off = 0; }
    else if (i < 147456) { src = s1; off = 110592; }
    else if (i < 294912) { src = s2; off = 147456; }
    else                 { src = s3; off = 294912; }
    const float4 v = *(const float4*)(src + (i - off));
    __half2* d = (__half2*)(dst + i);
    d[0] = __floats2half2_rn(v.x, v.y);
    d[1] = __floats2half2_rn(v.z, v.w);
}

// ---------------------------------------------------------------------------
// Fused window attention. Block per (window, head), 64 threads.
// ---------------------------------------------------------------------------
__global__ void __launch_bounds__(64)
attn_kernel(const __half* __restrict__ qkv,
            const float* __restrict__ rpb,
            __half* __restrict__ out)
{
    const int win  = blockIdx.x;
    const int head = blockIdx.y;
    const int n    = threadIdx.x;

    __shared__ float ks[64][36];
    __shared__ float vs[64][36];
    __shared__ float sp[64][65];
    __shared__ float sbias[225];
    __shared__ int   lab[64];

    const __half* base = qkv + (long)win * NPW * (3 * Cdim);
    const __half2* k2 = (const __half2*)(base + n * (3 * Cdim) + Cdim + head * HD);
    const __half2* v2 = (const __half2*)(base + n * (3 * Cdim) + 2 * Cdim + head * HD);
#pragma unroll
    for (int dp = 0; dp < 16; dp++) {
        const float2 fk = __half22float2(k2[dp]);
        const float2 fv = __half22float2(v2[dp]);
        ks[n][2 * dp] = fk.x; ks[n][2 * dp + 1] = fk.y;
        vs[n][2 * dp] = fv.x; vs[n][2 * dp + 1] = fv.y;
    }
    for (int idx = n; idx < 225; idx += 64) sbias[idx] = rpb[idx * NH + head];
    {
        const int wi = win & 255;
        const int gh = (wi >> 4) * 8 + (n >> 3);
        const int gw = (wi & 15) * 8 + (n & 7);
        const int rh = (gh < Himg - WS) ? 0 : ((gh < Himg - SHIFT) ? 1 : 2);
        const int rw = (gw < Wimg - WS) ? 0 : ((gw < Wimg - SHIFT) ? 1 : 2);
        lab[n] = rh * 3 + rw;
    }
    __syncthreads();

    float q[HD];
    const __half2* q2 = (const __half2*)(base + n * (3 * Cdim) + head * HD);
#pragma unroll
    for (int dp = 0; dp < 16; dp++) {
        const float2 f = __half22float2(q2[dp]);
        q[2 * dp]     = f.x * 0.17677669529663687f;
        q[2 * dp + 1] = f.y * 0.17677669529663687f;
    }

    const int i = n >> 3, j = n & 7;
    const int myl = lab[n];

    float mx = -1e30f;
    for (int m = 0; m < 64; m++) {
        const float4* kr = (const float4*)&ks[m][0];
        float s = 0.f;
#pragma unroll
        for (int t = 0; t < 8; t++) {
            const float4 kv = kr[t];
            s += q[4*t] * kv.x + q[4*t+1] * kv.y + q[4*t+2] * kv.z + q[4*t+3] * kv.w;
        }
        s += sbias[(i - (m >> 3) + 7) * 15 + (j - (m & 7) + 7)];
        if (lab[m] != myl) s -= 100.f;
        sp[n][m] = s;
        mx = fmaxf(mx, s);
    }
    float sum = 0.f;
    for (int m = 0; m < 64; m++) {
        const float e = expf(sp[n][m] - mx);
        sp[n][m] = e; sum += e;
    }
    const float inv = 1.f / sum;

    float accv[HD];
#pragma unroll
    for (int d = 0; d < HD; d++) accv[d] = 0.f;
    for (int m = 0; m < 64; m++) {
        const float p = sp[n][m];
        const float4* vr = (const float4*)&vs[m][0];
#pragma unroll
        for (int t = 0; t < 8; t++) {
            const float4 vv = vr[t];
            accv[4*t]   += p * vv.x;
            accv[4*t+1] += p * vv.y;
            accv[4*t+2] += p * vv.z;
            accv[4*t+3] += p * vv.w;
        }
    }
    __half* dst = out + ((long)win * NPW + n) * Cdim + head * HD;
#pragma unroll
    for (int dp = 0; dp < 16; dp++)
        *(__half2*)(dst + 2 * dp) = __floats2half2_rn(accv[2*dp] * inv, accv[2*dp+1] * inv);
}

// ---------------------------------------------------------------------------
// Launch
// ---------------------------------------------------------------------------
extern "C" void kernel_launch(void* const* d_in, const int* in_sizes, int n_in,
                              void* d_out, int out_size)
{
    const float* x      = (const float*)d_in[0];
    const float* g1     = (const float*)d_in[1];
    const float* b1     = (const float*)d_in[2];
    const float* qkv_w  = (const float*)d_in[3];
    const float* qkv_b  = (const float*)d_in[4];
    const float* rpb    = (const float*)d_in[5];
    const float* proj_w = (const float*)d_in[6];
    const float* proj_b = (const float*)d_in[7];
    const float* g2     = (const float*)d_in[8];
    const float* b2     = (const float*)d_in[9];
    const float* fc1_w  = (const float*)d_in[10];
    const float* fc1_b  = (const float*)d_in[11];
    const float* fc2_w  = (const float*)d_in[12];
    const float* fc2_b  = (const float*)d_in[13];
    float* out = (float*)d_out;

    __half *p_qkv, *p_att, *p_ln2, *p_hh, *p_wh;
    float *p_x1;
    cudaGetSymbolAddress((void**)&p_qkv, g_qkv);
    cudaGetSymbolAddress((void**)&p_att, g_att);
    cudaGetSymbolAddress((void**)&p_ln2, g_ln2);
    cudaGetSymbolAddress((void**)&p_hh,  g_hh);
    cudaGetSymbolAddress((void**)&p_x1,  g_x1);
    cudaGetSymbolAddress((void**)&p_wh,  g_wh);

    static bool attr_set = false;
    if (!attr_set) {
        cudaFuncSetAttribute(gemm_ln, cudaFuncAttributeMaxDynamicSharedMemorySize, LN_SMEM);
        cudaFuncSetAttribute(gemm_ha, cudaFuncAttributeMaxDynamicSharedMemorySize, HA_SMEM);
        cudaFuncSetAttribute(gemm_h<3>, cudaFuncAttributeMaxDynamicSharedMemorySize, GEMM_SMEM);
        cudaFuncSetAttribute(gemm_h<2>, cudaFuncAttributeMaxDynamicSharedMemorySize, GEMM_SMEM);
        attr_set = true;
    }

    __half* w_qkv = p_wh;
    __half* w_prj = p_wh + 110592;
    __half* w_fc1 = p_wh + 147456;
    __half* w_fc2 = p_wh + 294912;

    // 0. weights fp32 -> fp16 (single launch)
    tohalf_all<<<442368 / 1024, 256>>>(qkv_w, proj_w, fc1_w, fc2_w, p_wh);

    const int M = NTOK;  // 131072, 1024 M-tiles

    // 1. QKV (fused LN1 + shift/window gather)
    gemm_ln<<<M / 128, 256, LN_SMEM>>>(x, w_qkv, qkv_b, g1, b1, p_qkv, 3 * Cdim);

    // 2. Window attention
    attn_kernel<<<dim3(NWIN, NH), 64>>>(p_qkv, rpb, p_att);

    // 3. proj + unshift + x residual -> x1 fp32; fused LN2 -> ln2 half
    gemm_h<3><<<dim3(M / 128, 1), 256, GEMM_SMEM>>>(
        p_att, w_prj, proj_b, x, p_x1, p_ln2, g2, b2, Cdim, Cdim);

    // 4. FC1 + GELU (A-resident): hh[M,768] half
    gemm_ha<<<M / 128, 256, HA_SMEM>>>(p_ln2, w_fc1, fc1_b, p_hh, HID);

    // 5. FC2 + x1 residual -> out fp32
    gemm_h<2><<<dim3(M / 128, 1), 256, GEMM_SMEM>>>(
        p_hh, w_fc2, fc2_b, p_x1, out, nullptr, nullptr, nullptr, Cdim, HID);
}

// round 7
// speedup vs baseline: 4.2241x; 1.0334x over previous
#include <cuda_runtime.h>
#include <cuda_fp16.h>
#include <math.h>
#include <stdint.h>

// ---------------------------------------------------------------------------
// Problem constants
// ---------------------------------------------------------------------------
#define Bsz   8
#define Himg  128
#define Wimg  128
#define Cdim  192
#define HID   768
#define WS    8
#define SHIFT 4
#define NH    6
#define HD    32
#define NTOK  (Bsz*Himg*Wimg)             // 131072
#define NWIN  2048
#define NPW   64

// ---------------------------------------------------------------------------
// Scratch
// ---------------------------------------------------------------------------
__device__ __align__(16) __half g_qkv[(size_t)NTOK * 3 * Cdim];
__device__ __align__(16) __half g_att[(size_t)NTOK * Cdim];
__device__ __align__(16) __half g_ln2[(size_t)NTOK * Cdim];
__device__ __align__(16) __half g_hh [(size_t)NTOK * HID];
__device__ __align__(16) float  g_x1 [(size_t)NTOK * Cdim];
__device__ __align__(16) __half g_wh[442368];   // qkv@0 proj@110592 fc1@147456 fc2@294912

// ---------------------------------------------------------------------------
// Helpers
// ---------------------------------------------------------------------------
__device__ __forceinline__ uint32_t smem_u32(const void* p) {
    uint32_t a;
    asm("{ .reg .u64 t; cvta.to.shared.u64 t, %1; cvt.u32.u64 %0, t; }" : "=r"(a) : "l"(p));
    return a;
}
__device__ __forceinline__ void cp_async16(uint32_t dst, const void* src) {
    asm volatile("cp.async.cg.shared.global [%0], [%1], 16;" :: "r"(dst), "l"(src) : "memory");
}
__device__ __forceinline__ uint32_t lds32(uint32_t addr) {
    uint32_t v;
    asm volatile("ld.shared.b32 %0, [%1];" : "=r"(v) : "r"(addr));
    return v;
}
__device__ __forceinline__ void sts32(uint32_t addr, uint32_t v) {
    asm volatile("st.shared.b32 [%0], %1;" :: "r"(addr), "r"(v) : "memory");
}
__device__ __forceinline__ void mma16(float* c, const uint32_t* a, const uint32_t* b) {
    asm volatile("mma.sync.aligned.m16n8k16.row.col.f32.f16.f16.f32 "
        "{%0,%1,%2,%3}, {%4,%5,%6,%7}, {%8,%9}, {%0,%1,%2,%3};"
        : "+f"(c[0]), "+f"(c[1]), "+f"(c[2]), "+f"(c[3])
        : "r"(a[0]), "r"(a[1]), "r"(a[2]), "r"(a[3]), "r"(b[0]), "r"(b[1]));
}
__device__ __forceinline__ long win2orig(long t) {
    const int b_ = (int)(t >> 6), n = (int)(t & 63);
    const int b = b_ >> 8, wi = b_ & 255;
    const int h = ((wi >> 4) * 8 + (n >> 3) + SHIFT) & 127;
    const int w = ((wi & 15) * 8 + (n & 7) + SHIFT) & 127;
    return ((long)b * 128 + h) * 128 + w;
}

#define ACHUNK 16384   // 128 rows x 128B
#define BCHUNK 24576   // 192 rows x 128B
#define NTHREADS 512

// common warp/lane decomposition (16 warps: 4m x 4n, warp tile 32x48)
#define DECOMP() \
    const int tid  = threadIdx.x; \
    const int wid  = tid >> 5; \
    const int lane = tid & 31; \
    const int g    = lane >> 2; \
    const int tig  = lane & 3; \
    const int m0w  = (wid >> 2) * 32; \
    const int n0w  = (wid & 3) * 48;

// inner k-chunk compute: 4 k-steps over aRow/bRow, acc[2][6][4]
#define KCHUNK_MMA(aRow, bRow) \
    _Pragma("unroll") \
    for (int s = 0; s < 4; s++) { \
        const uint32_t koff0 = (uint32_t)(((2 * s) ^ g) << 4); \
        const uint32_t koff1 = koff0 ^ 16u; \
        uint32_t af[2][4]; \
        _Pragma("unroll") \
        for (int mi = 0; mi < 2; mi++) { \
            const uint32_t p = (aRow) + mi * 2048; \
            af[mi][0] = lds32(p + koff0); \
            af[mi][1] = lds32(p + 1024 + koff0); \
            af[mi][2] = lds32(p + koff1); \
            af[mi][3] = lds32(p + 1024 + koff1); \
        } \
        uint32_t bf[6][2]; \
        _Pragma("unroll") \
        for (int ni = 0; ni < 6; ni++) { \
            const uint32_t p = (bRow) + ni * 1024; \
            bf[ni][0] = lds32(p + koff0); \
            bf[ni][1] = lds32(p + koff1); \
        } \
        _Pragma("unroll") \
        for (int mi = 0; mi < 2; mi++) \
            _Pragma("unroll") \
            for (int ni = 0; ni < 6; ni++) \
                mma16(acc[mi][ni], af[mi], bf[ni]); \
    }

#define CLEAR_ACC() \
    _Pragma("unroll") \
    for (int mi = 0; mi < 2; mi++) \
        _Pragma("unroll") \
        for (int ni = 0; ni < 6; ni++) \
            _Pragma("unroll") \
            for (int c = 0; c < 4; c++) acc[mi][ni][c] = 0.f;

// B chunk loader (192 rows): lm = tid>>3 (0..63), 3 iterations of 64 rows
#define ISSUE_B(buf, nt, c) do { \
        const uint32_t bd = bBase + (uint32_t)(buf) * BCHUNK + (uint32_t)lm * 128 + bswz; \
        const __half* sb = B + ((long)(nt) * 192 + lm) * Cdim + (c) * 64 + lq * 8; \
        _Pragma("unroll") \
        for (int it = 0; it < 3; it++) \
            cp_async16(bd + it * 8192, sb + (long)it * 64 * Cdim); \
        asm volatile("cp.async.commit_group;" ::: "memory"); \
    } while (0)

// ---------------------------------------------------------------------------
// Fused LN + GEMM (QKV): C[M,N] = LN(gather(A))[M,192] @ B[N,192]^T + bias
// ---------------------------------------------------------------------------
#define LN_SMEM (3*ACHUNK + 2*BCHUNK + 128)

__global__ void __launch_bounds__(NTHREADS, 1)
gemm_ln(const float* __restrict__ Asrc, const __half* __restrict__ B,
        const float* __restrict__ bias, const float* __restrict__ gamma,
        const float* __restrict__ beta, __half* __restrict__ C, int N)
{
    extern __shared__ char dsm[];
    const uint32_t base  = (smem_u32(dsm) + 127u) & ~127u;
    const uint32_t bBase = base + 3 * ACHUNK;

    DECOMP();
    const long m0 = (long)blockIdx.x * 128;
    const int lm = tid >> 3;
    const int lq = tid & 7;
    const uint32_t bswz = (uint32_t)((lq ^ (lm & 7)) << 4);
    const int NT = N / 192;

    ISSUE_B(0, 0, 0);

    // Phase 1: LN of gathered A (each warp: 8 rows)
#pragma unroll 1
    for (int rr = 0; rr < 8; rr++) {
        const int row = wid * 8 + rr;
        const long t = m0 + row;
        const float* src = Asrc + win2orig(t) * Cdim;
        float2 v[3];
        float s = 0.f, ss = 0.f;
#pragma unroll
        for (int i = 0; i < 3; i++) {
            v[i] = *(const float2*)(src + 2 * lane + 64 * i);
            s  += v[i].x + v[i].y;
            ss += v[i].x * v[i].x + v[i].y * v[i].y;
        }
#pragma unroll
        for (int o = 16; o > 0; o >>= 1) {
            s  += __shfl_xor_sync(0xffffffffu, s,  o);
            ss += __shfl_xor_sync(0xffffffffu, ss, o);
        }
        const float mu  = s * (1.f / Cdim);
        const float var = ss * (1.f / Cdim) - mu * mu;
        const float r   = rsqrtf(var + 1e-5f);
        const uint32_t rowaddr = base + (uint32_t)row * 128 +
            ((((uint32_t)lane >> 2) ^ ((uint32_t)row & 7)) << 4) + ((uint32_t)lane & 3) * 4;
#pragma unroll
        for (int i = 0; i < 3; i++) {
            const int c = 2 * lane + 64 * i;
            const float2 gm = *(const float2*)(gamma + c);
            const float2 bt = *(const float2*)(beta + c);
            const __half2 hv = __floats2half2_rn((v[i].x - mu) * r * gm.x + bt.x,
                                                 (v[i].y - mu) * r * gm.y + bt.y);
            sts32(rowaddr + (uint32_t)i * ACHUNK, *(const uint32_t*)&hv);
        }
    }

    const uint32_t aRowOff = (uint32_t)(m0w + g) * 128 + (uint32_t)tig * 4;
    const uint32_t bRowOff = (uint32_t)(n0w + g) * 128 + (uint32_t)tig * 4;

    float acc[2][6][4];
    CLEAR_ACC();

    const int total = NT * 3;
    for (int ci = 0; ci < total; ci++) {
        const int c = ci % 3;
        if (ci + 1 < total) {
            const int cn = ci + 1;
            ISSUE_B(cn & 1, cn / 3, cn % 3);
            asm volatile("cp.async.wait_group 1;" ::: "memory");
        } else {
            asm volatile("cp.async.wait_group 0;" ::: "memory");
        }
        __syncthreads();

        const uint32_t aRow = base + (uint32_t)c * ACHUNK + aRowOff;
        const uint32_t bRow = bBase + (uint32_t)(ci & 1) * BCHUNK + bRowOff;
        KCHUNK_MMA(aRow, bRow);

        if (c == 2) {
            const int nt = ci / 3;
#pragma unroll
            for (int mi = 0; mi < 2; mi++) {
                const long r0 = m0 + m0w + mi * 16 + g;
                const long r1 = r0 + 8;
#pragma unroll
                for (int ni = 0; ni < 6; ni++) {
                    const int col = nt * 192 + n0w + ni * 8 + 2 * tig;
                    const float b0 = bias[col], b1 = bias[col + 1];
                    *(__half2*)(C + r0 * N + col) =
                        __floats2half2_rn(acc[mi][ni][0] + b0, acc[mi][ni][1] + b1);
                    *(__half2*)(C + r1 * N + col) =
                        __floats2half2_rn(acc[mi][ni][2] + b0, acc[mi][ni][3] + b1);
                    acc[mi][ni][0] = 0.f; acc[mi][ni][1] = 0.f;
                    acc[mi][ni][2] = 0.f; acc[mi][ni][3] = 0.f;
                }
            }
        }
        __syncthreads();
    }
}

// ---------------------------------------------------------------------------
// A-resident fp16 GEMM (FC1): C = GELU(A[M,192] @ B[N,192]^T + bias), half out
// ---------------------------------------------------------------------------
#define HA_SMEM (3*ACHUNK + 2*BCHUNK + 128)

__global__ void __launch_bounds__(NTHREADS, 1)
gemm_ha(const __half* __restrict__ A, const __half* __restrict__ B,
        const float* __restrict__ bias, __half* __restrict__ C, int N)
{
    extern __shared__ char dsm[];
    const uint32_t base  = (smem_u32(dsm) + 127u) & ~127u;
    const uint32_t bBase = base + 3 * ACHUNK;

    DECOMP();
    const long m0 = (long)blockIdx.x * 128;
    const int lm = tid >> 3;
    const int lq = tid & 7;
    const uint32_t bswz = (uint32_t)((lq ^ (lm & 7)) << 4);
    const int NT = N / 192;

    // A resident: 128 rows x 3 chunks; lm covers 0..63, 2 row-groups
    {
        const uint32_t da = base + (uint32_t)lm * 128 + bswz;
        const __half* sa = A + (m0 + lm) * Cdim + lq * 8;
#pragma unroll
        for (int c = 0; c < 3; c++)
#pragma unroll
            for (int it = 0; it < 2; it++)
                cp_async16(da + (uint32_t)c * ACHUNK + it * 8192,
                           sa + (long)it * 64 * Cdim + c * 64);
        asm volatile("cp.async.commit_group;" ::: "memory");
    }

    ISSUE_B(0, 0, 0);

    const uint32_t aRowOff = (uint32_t)(m0w + g) * 128 + (uint32_t)tig * 4;
    const uint32_t bRowOff = (uint32_t)(n0w + g) * 128 + (uint32_t)tig * 4;

    float acc[2][6][4];
    CLEAR_ACC();

    const int total = NT * 3;
    for (int ci = 0; ci < total; ci++) {
        const int c = ci % 3;
        if (ci + 1 < total) {
            const int cn = ci + 1;
            ISSUE_B(cn & 1, cn / 3, cn % 3);
            asm volatile("cp.async.wait_group 1;" ::: "memory");
        } else {
            asm volatile("cp.async.wait_group 0;" ::: "memory");
        }
        __syncthreads();

        const uint32_t aRow = base + (uint32_t)c * ACHUNK + aRowOff;
        const uint32_t bRow = bBase + (uint32_t)(ci & 1) * BCHUNK + bRowOff;
        KCHUNK_MMA(aRow, bRow);

        if (c == 2) {
            const int nt = ci / 3;
#pragma unroll
            for (int mi = 0; mi < 2; mi++) {
                const long r0 = m0 + m0w + mi * 16 + g;
                const long r1 = r0 + 8;
#pragma unroll
                for (int ni = 0; ni < 6; ni++) {
                    const int col = nt * 192 + n0w + ni * 8 + 2 * tig;
                    const float b0 = bias[col], b1 = bias[col + 1];
                    float v0 = acc[mi][ni][0] + b0;
                    float v1 = acc[mi][ni][1] + b1;
                    float v2 = acc[mi][ni][2] + b0;
                    float v3 = acc[mi][ni][3] + b1;
                    v0 = 0.5f * v0 * (1.f + erff(v0 * 0.7071067811865475f));
                    v1 = 0.5f * v1 * (1.f + erff(v1 * 0.7071067811865475f));
                    v2 = 0.5f * v2 * (1.f + erff(v2 * 0.7071067811865475f));
                    v3 = 0.5f * v3 * (1.f + erff(v3 * 0.7071067811865475f));
                    *(__half2*)(C + r0 * N + col) = __floats2half2_rn(v0, v1);
                    *(__half2*)(C + r1 * N + col) = __floats2half2_rn(v2, v3);
                    acc[mi][ni][0] = 0.f; acc[mi][ni][1] = 0.f;
                    acc[mi][ni][2] = 0.f; acc[mi][ni][3] = 0.f;
                }
            }
        }
        __syncthreads();
    }
}

// ---------------------------------------------------------------------------
// Streaming fp16 GEMM.
// EPI=2: FC2 (+res fp32 -> out fp32)
// EPI=3: proj (unshift + x residual -> x1 fp32, LN2 -> ln2 half)
// ---------------------------------------------------------------------------
#define ASTAGE 16384
#define BSTAGE 24576
#define STAGE  (ASTAGE + BSTAGE)
#define GEMM_SMEM (2*STAGE + 128)

template <int EPI>
__global__ void __launch_bounds__(NTHREADS, 1)
gemm_h(const __half* __restrict__ A, const __half* __restrict__ Bw,
       const float* __restrict__ bias, const float* __restrict__ res,
       float* __restrict__ C, __half* __restrict__ C2,
       const float* __restrict__ gamma, const float* __restrict__ beta,
       int N, int K)
{
    extern __shared__ char dsm[];
    const uint32_t base = (smem_u32(dsm) + 127u) & ~127u;

    DECOMP();
    const long m0 = (long)blockIdx.x * 128;
    const int  n0 = blockIdx.y * 192;

    const int lm = tid >> 3;
    const int lq = tid & 7;
    const __half* srcA = A + (m0 + lm) * K + lq * 8;
    const __half* srcB = Bw + (long)(n0 + lm) * K + lq * 8;
    const uint32_t swz = (uint32_t)((lq ^ (lm & 7)) << 4);
    const uint32_t dstA0 = base + (uint32_t)lm * 128 + swz;
    const uint32_t dstB0 = base + ASTAGE + (uint32_t)lm * 128 + swz;

    float acc[2][6][4];
    CLEAR_ACC();

    const int NC = K >> 6;

#define ISSUE(buf, kc_) do { \
        const uint32_t so = (uint32_t)(buf) * STAGE; \
        const __half* sa = srcA + (kc_); \
        const __half* sb = srcB + (kc_); \
        _Pragma("unroll") \
        for (int it = 0; it < 2; it++) \
            cp_async16(dstA0 + so + it * 8192, sa + (long)it * 64 * K); \
        _Pragma("unroll") \
        for (int it = 0; it < 3; it++) \
            cp_async16(dstB0 + so + it * 8192, sb + (long)it * 64 * K); \
        asm volatile("cp.async.commit_group;" ::: "memory"); \
    } while (0)

    ISSUE(0, 0);

    const uint32_t aRow0 = base + (uint32_t)(m0w + g) * 128 + (uint32_t)tig * 4;
    const uint32_t bRow0 = base + ASTAGE + (uint32_t)(n0w + g) * 128 + (uint32_t)tig * 4;

    for (int i = 0; i < NC; i++) {
        if (i + 1 < NC) {
            ISSUE((i + 1) & 1, (i + 1) << 6);
            asm volatile("cp.async.wait_group 1;" ::: "memory");
        } else {
            asm volatile("cp.async.wait_group 0;" ::: "memory");
        }
        __syncthreads();

        const uint32_t so = (uint32_t)(i & 1) * STAGE;
        const uint32_t aRow = aRow0 + so;
        const uint32_t bRow = bRow0 + so;
        KCHUNK_MMA(aRow, bRow);
        __syncthreads();
    }
#undef ISSUE

    // bias + residual into acc
#pragma unroll
    for (int mi = 0; mi < 2; mi++) {
        const long rw0 = m0 + m0w + mi * 16 + g;
        const long rw1 = rw0 + 8;
        const long r0 = (EPI == 3) ? win2orig(rw0) : rw0;
        const long r1 = (EPI == 3) ? win2orig(rw1) : rw1;
#pragma unroll
        for (int ni = 0; ni < 6; ni++) {
            const int col = n0 + n0w + ni * 8 + 2 * tig;
            const float b0 = bias[col], b1 = bias[col + 1];
            const float2 ra = *(const float2*)(res + r0 * N + col);
            const float2 rb = *(const float2*)(res + r1 * N + col);
            acc[mi][ni][0] += b0 + ra.x;
            acc[mi][ni][1] += b1 + ra.y;
            acc[mi][ni][2] += b0 + rb.x;
            acc[mi][ni][3] += b1 + rb.y;
        }
    }

    if (EPI == 3) {
        float* rsum   = (float*)(dsm);
        float* rsumsq = rsum + 128;
        if (tid < 128) { rsum[tid] = 0.f; rsumsq[tid] = 0.f; }
        __syncthreads();
#pragma unroll
        for (int mi = 0; mi < 2; mi++) {
            const int row0 = m0w + mi * 16 + g;
            float s0 = 0.f, q0 = 0.f, s1 = 0.f, q1 = 0.f;
#pragma unroll
            for (int ni = 0; ni < 6; ni++) {
                s0 += acc[mi][ni][0] + acc[mi][ni][1];
                q0 += acc[mi][ni][0] * acc[mi][ni][0] + acc[mi][ni][1] * acc[mi][ni][1];
                s1 += acc[mi][ni][2] + acc[mi][ni][3];
                q1 += acc[mi][ni][2] * acc[mi][ni][2] + acc[mi][ni][3] * acc[mi][ni][3];
            }
            atomicAdd(&rsum[row0], s0);     atomicAdd(&rsumsq[row0], q0);
            atomicAdd(&rsum[row0 + 8], s1); atomicAdd(&rsumsq[row0 + 8], q1);
        }
        __syncthreads();
    }

#pragma unroll
    for (int mi = 0; mi < 2; mi++) {
        const long rw0 = m0 + m0w + mi * 16 + g;
        const long rw1 = rw0 + 8;
        const long r0 = (EPI == 3) ? win2orig(rw0) : rw0;
        const long r1 = (EPI == 3) ? win2orig(rw1) : rw1;

        float mu0 = 0.f, rs0 = 0.f, mu1 = 0.f, rs1 = 0.f;
        if (EPI == 3) {
            const float* rsum   = (const float*)(dsm);
            const float* rsumsq = rsum + 128;
            const int row0 = m0w + mi * 16 + g;
            mu0 = rsum[row0] * (1.f / Cdim);
            rs0 = rsqrtf(rsumsq[row0] * (1.f / Cdim) - mu0 * mu0 + 1e-5f);
            mu1 = rsum[row0 + 8] * (1.f / Cdim);
            rs1 = rsqrtf(rsumsq[row0 + 8] * (1.f / Cdim) - mu1 * mu1 + 1e-5f);
        }
#pragma unroll
        for (int ni = 0; ni < 6; ni++) {
            const int col = n0 + n0w + ni * 8 + 2 * tig;
            const float v0 = acc[mi][ni][0], v1 = acc[mi][ni][1];
            const float v2 = acc[mi][ni][2], v3 = acc[mi][ni][3];
            *(float2*)(C + r0 * N + col) = make_float2(v0, v1);
            *(float2*)(C + r1 * N + col) = make_float2(v2, v3);
            if (EPI == 3) {
                const float2 gm = *(const float2*)(gamma + col);
                const float2 bt = *(const float2*)(beta + col);
                *(__half2*)(C2 + r0 * N + col) = __floats2half2_rn(
                    (v0 - mu0) * rs0 * gm.x + bt.x, (v1 - mu0) * rs0 * gm.y + bt.y);
                *(__half2*)(C2 + r1 * N + col) = __floats2half2_rn(
                    (v2 - mu1) * rs1 * gm.x + bt.x, (v3 - mu1) * rs1 * gm.y + bt.y);
            }
        }
    }
}

// ---------------------------------------------------------------------------
// One-shot weight conversion fp32 -> fp16 (4 tensors)
// ---------------------------------------------------------------------------
__global__ void tohalf_all(const float* __restrict__ s0, const float* __restrict__ s1,
                           const float* __restrict__ s2, const float* __restrict__ s3,
                           __half* __restrict__ dst)
{
    const int i = blockIdx.x * 1024 + threadIdx.x * 4;
    const float* src;
    int off;
    if (i < 110592)      { src = s0; off = 0; }
    else if (i < 147456) { src = s1; off = 110592; }
    else if (i < 294912) { src = s2; off = 147456; }
    else                 { src = s3; off = 294912; }
    const float4 v = *(const float4*)(src + (i - off));
    __half2* d = (__half2*)(dst + i);
    d[0] = __floats2half2_rn(v.x, v.y);
    d[1] = __floats2half2_rn(v.z, v.w);
}

// ---------------------------------------------------------------------------
// Fused window attention. Block per (window, head), 64 threads.
// ---------------------------------------------------------------------------
__global__ void __launch_bounds__(64)
attn_kernel(const __half* __restrict__ qkv,
            const float* __restrict__ rpb,
            __half* __restrict__ out)
{
    const int win  = blockIdx.x;
    const int head = blockIdx.y;
    const int n    = threadIdx.x;

    __shared__ float ks[64][36];
    __shared__ float vs[64][36];
    __shared__ float sp[64][65];
    __shared__ float sbias[225];
    __shared__ int   lab[64];

    const __half* base = qkv + (long)win * NPW * (3 * Cdim);
    const __half2* k2 = (const __half2*)(base + n * (3 * Cdim) + Cdim + head * HD);
    const __half2* v2 = (const __half2*)(base + n * (3 * Cdim) + 2 * Cdim + head * HD);
#pragma unroll
    for (int dp = 0; dp < 16; dp++) {
        const float2 fk = __half22float2(k2[dp]);
        const float2 fv = __half22float2(v2[dp]);
        ks[n][2 * dp] = fk.x; ks[n][2 * dp + 1] = fk.y;
        vs[n][2 * dp] = fv.x; vs[n][2 * dp + 1] = fv.y;
    }
    for (int idx = n; idx < 225; idx += 64) sbias[idx] = rpb[idx * NH + head];
    {
        const int wi = win & 255;
        const int gh = (wi >> 4) * 8 + (n >> 3);
        const int gw = (wi & 15) * 8 + (n & 7);
        const int rh = (gh < Himg - WS) ? 0 : ((gh < Himg - SHIFT) ? 1 : 2);
        const int rw = (gw < Wimg - WS) ? 0 : ((gw < Wimg - SHIFT) ? 1 : 2);
        lab[n] = rh * 3 + rw;
    }
    __syncthreads();

    float q[HD];
    const __half2* q2 = (const __half2*)(base + n * (3 * Cdim) + head * HD);
#pragma unroll
    for (int dp = 0; dp < 16; dp++) {
        const float2 f = __half22float2(q2[dp]);
        q[2 * dp]     = f.x * 0.17677669529663687f;
        q[2 * dp + 1] = f.y * 0.17677669529663687f;
    }

    const int i = n >> 3, j = n & 7;
    const int myl = lab[n];

    float mx = -1e30f;
    for (int m = 0; m < 64; m++) {
        const float4* kr = (const float4*)&ks[m][0];
        float s = 0.f;
#pragma unroll
        for (int t = 0; t < 8; t++) {
            const float4 kv = kr[t];
            s += q[4*t] * kv.x + q[4*t+1] * kv.y + q[4*t+2] * kv.z + q[4*t+3] * kv.w;
        }
        s += sbias[(i - (m >> 3) + 7) * 15 + (j - (m & 7) + 7)];
        if (lab[m] != myl) s -= 100.f;
        sp[n][m] = s;
        mx = fmaxf(mx, s);
    }
    float sum = 0.f;
    for (int m = 0; m < 64; m++) {
        const float e = expf(sp[n][m] - mx);
        sp[n][m] = e; sum += e;
    }
    const float inv = 1.f / sum;

    float accv[HD];
#pragma unroll
    for (int d = 0; d < HD; d++) accv[d] = 0.f;
    for (int m = 0; m < 64; m++) {
        const float p = sp[n][m];
        const float4* vr = (const float4*)&vs[m][0];
#pragma unroll
        for (int t = 0; t < 8; t++) {
            const float4 vv = vr[t];
            accv[4*t]   += p * vv.x;
            accv[4*t+1] += p * vv.y;
            accv[4*t+2] += p * vv.z;
            accv[4*t+3] += p * vv.w;
        }
    }
    __half* dst = out + ((long)win * NPW + n) * Cdim + head * HD;
#pragma unroll
    for (int dp = 0; dp < 16; dp++)
        *(__half2*)(dst + 2 * dp) = __floats2half2_rn(accv[2*dp] * inv, accv[2*dp+1] * inv);
}

// ---------------------------------------------------------------------------
// Launch
// ---------------------------------------------------------------------------
extern "C" void kernel_launch(void* const* d_in, const int* in_sizes, int n_in,
                              void* d_out, int out_size)
{
    const float* x      = (const float*)d_in[0];
    const float* g1     = (const float*)d_in[1];
    const float* b1     = (const float*)d_in[2];
    const float* qkv_w  = (const float*)d_in[3];
    const float* qkv_b  = (const float*)d_in[4];
    const float* rpb    = (const float*)d_in[5];
    const float* proj_w = (const float*)d_in[6];
    const float* proj_b = (const float*)d_in[7];
    const float* g2     = (const float*)d_in[8];
    const float* b2     = (const float*)d_in[9];
    const float* fc1_w  = (const float*)d_in[10];
    const float* fc1_b  = (const float*)d_in[11];
    const float* fc2_w  = (const float*)d_in[12];
    const float* fc2_b  = (const float*)d_in[13];
    float* out = (float*)d_out;

    __half *p_qkv, *p_att, *p_ln2, *p_hh, *p_wh;
    float *p_x1;
    cudaGetSymbolAddress((void**)&p_qkv, g_qkv);
    cudaGetSymbolAddress((void**)&p_att, g_att);
    cudaGetSymbolAddress((void**)&p_ln2, g_ln2);
    cudaGetSymbolAddress((void**)&p_hh,  g_hh);
    cudaGetSymbolAddress((void**)&p_x1,  g_x1);
    cudaGetSymbolAddress((void**)&p_wh,  g_wh);

    static bool attr_set = false;
    if (!attr_set) {
        cudaFuncSetAttribute(gemm_ln, cudaFuncAttributeMaxDynamicSharedMemorySize, LN_SMEM);
        cudaFuncSetAttribute(gemm_ha, cudaFuncAttributeMaxDynamicSharedMemorySize, HA_SMEM);
        cudaFuncSetAttribute(gemm_h<3>, cudaFuncAttributeMaxDynamicSharedMemorySize, GEMM_SMEM);
        cudaFuncSetAttribute(gemm_h<2>, cudaFuncAttributeMaxDynamicSharedMemorySize, GEMM_SMEM);
        attr_set = true;
    }

    __half* w_qkv = p_wh;
    __half* w_prj = p_wh + 110592;
    __half* w_fc1 = p_wh + 147456;
    __half* w_fc2 = p_wh + 294912;

    // 0. weights fp32 -> fp16
    tohalf_all<<<442368 / 1024, 256>>>(qkv_w, proj_w, fc1_w, fc2_w, p_wh);

    const int M = NTOK;  // 131072, 1024 M-tiles

    // 1. QKV (fused LN1 + shift/window gather)
    gemm_ln<<<M / 128, NTHREADS, LN_SMEM>>>(x, w_qkv, qkv_b, g1, b1, p_qkv, 3 * Cdim);

    // 2. Window attention
    attn_kernel<<<dim3(NWIN, NH), 64>>>(p_qkv, rpb, p_att);

    // 3. proj + unshift + x residual -> x1 fp32; fused LN2 -> ln2 half
    gemm_h<3><<<dim3(M / 128, 1), NTHREADS, GEMM_SMEM>>>(
        p_att, w_prj, proj_b, x, p_x1, p_ln2, g2, b2, Cdim, Cdim);

    // 4. FC1 + GELU (A-resident)
    gemm_ha<<<M / 128, NTHREADS, HA_SMEM>>>(p_ln2, w_fc1, fc1_b, p_hh, HID);

    // 5. FC2 + x1 residual -> out fp32
    gemm_h<2><<<dim3(M / 128, 1), NTHREADS, GEMM_SMEM>>>(
        p_hh, w_fc2, fc2_b, p_x1, out, nullptr, nullptr, nullptr, Cdim, HID);
}

// round 8
// speedup vs baseline: 4.2723x; 1.0114x over previous
#include <cuda_runtime.h>
#include <cuda_fp16.h>
#include <math.h>
#include <stdint.h>

// ---------------------------------------------------------------------------
// Problem constants
// ---------------------------------------------------------------------------
#define Bsz   8
#define Himg  128
#define Wimg  128
#define Cdim  192
#define HID   768
#define WS    8
#define SHIFT 4
#define NH    6
#define HD    32
#define NTOK  (Bsz*Himg*Wimg)             // 131072
#define NWIN  2048
#define NPW   64

// ---------------------------------------------------------------------------
// Scratch
// ---------------------------------------------------------------------------
__device__ __align__(16) __half g_qkv[(size_t)NTOK * 3 * Cdim];
__device__ __align__(16) __half g_att[(size_t)NTOK * Cdim];
__device__ __align__(16) __half g_ln2[(size_t)NTOK * Cdim];
__device__ __align__(16) __half g_hh [(size_t)NTOK * HID];
__device__ __align__(16) float  g_x1 [(size_t)NTOK * Cdim];
__device__ __align__(16) __half g_wh[442368];   // qkv@0 proj@110592 fc1@147456 fc2@294912

// ---------------------------------------------------------------------------
// Helpers
// ---------------------------------------------------------------------------
__device__ __forceinline__ uint32_t smem_u32(const void* p) {
    uint32_t a;
    asm("{ .reg .u64 t; cvta.to.shared.u64 t, %1; cvt.u32.u64 %0, t; }" : "=r"(a) : "l"(p));
    return a;
}
__device__ __forceinline__ void cp_async16(uint32_t dst, const void* src) {
    asm volatile("cp.async.cg.shared.global [%0], [%1], 16;" :: "r"(dst), "l"(src) : "memory");
}
__device__ __forceinline__ void sts32(uint32_t addr, uint32_t v) {
    asm volatile("st.shared.b32 [%0], %1;" :: "r"(addr), "r"(v) : "memory");
}
__device__ __forceinline__ void ldsm4(uint32_t* r, uint32_t addr) {
    asm volatile("ldmatrix.sync.aligned.m8n8.x4.shared.b16 {%0,%1,%2,%3}, [%4];"
        : "=r"(r[0]), "=r"(r[1]), "=r"(r[2]), "=r"(r[3]) : "r"(addr));
}
__device__ __forceinline__ void mma16(float* c, const uint32_t* a, const uint32_t* b) {
    asm volatile("mma.sync.aligned.m16n8k16.row.col.f32.f16.f16.f32 "
        "{%0,%1,%2,%3}, {%4,%5,%6,%7}, {%8,%9}, {%0,%1,%2,%3};"
        : "+f"(c[0]), "+f"(c[1]), "+f"(c[2]), "+f"(c[3])
        : "r"(a[0]), "r"(a[1]), "r"(a[2]), "r"(a[3]), "r"(b[0]), "r"(b[1]));
}
__device__ __forceinline__ long win2orig(long t) {
    const int b_ = (int)(t >> 6), n = (int)(t & 63);
    const int b = b_ >> 8, wi = b_ & 255;
    const int h = ((wi >> 4) * 8 + (n >> 3) + SHIFT) & 127;
    const int w = ((wi & 15) * 8 + (n & 7) + SHIFT) & 127;
    return ((long)b * 128 + h) * 128 + w;
}

#define ACHUNK 16384   // 128 rows x 128B
#define BCHUNK 24576   // 192 rows x 128B
#define NTHREADS 512

// 16 warps: 4m x 4n, warp tile 32x48
#define DECOMP() \
    const int tid  = threadIdx.x; \
    const int wid  = tid >> 5; \
    const int lane = tid & 31; \
    const int g    = lane >> 2; \
    const int tig  = lane & 3; \
    const int m0w  = (wid >> 2) * 32; \
    const int n0w  = (wid & 3) * 48;

// ldmatrix per-lane constants. A: mats {r0-7 k0, r8-15 k0, r0-7 k8, r8-15 k8};
// B x4 covers 2 n-tiles: mats {n0-7 k0, n0-7 k8, n8-15 k0, n8-15 k8}.
#define LDSM_SETUP() \
    const int l8 = lane & 7; \
    const int aHi = lane >> 4; \
    const uint32_t aOff0 = (uint32_t)(m0w + l8 + ((lane >> 3) & 1) * 8) * 128; \
    const int bHi = (lane >> 3) & 1; \
    const uint32_t bOff0 = (uint32_t)(n0w + l8 + ((lane >> 4) & 1) * 8) * 128;

// one 64-half k-chunk: 4 k-steps; aB/bB are chunk base smem addresses
#define KCHUNK_MMA(aB, bB) \
    _Pragma("unroll") \
    for (int s = 0; s < 4; s++) { \
        const uint32_t ac = (uint32_t)(((2 * s + aHi) ^ l8) << 4); \
        const uint32_t bc = (uint32_t)(((2 * s + bHi) ^ l8) << 4); \
        uint32_t af[2][4], bp[3][4]; \
        _Pragma("unroll") \
        for (int mi = 0; mi < 2; mi++) ldsm4(af[mi], (aB) + aOff0 + mi * 2048 + ac); \
        _Pragma("unroll") \
        for (int p = 0; p < 3; p++)  ldsm4(bp[p], (bB) + bOff0 + p * 2048 + bc); \
        _Pragma("unroll") \
        for (int mi = 0; mi < 2; mi++) \
            _Pragma("unroll") \
            for (int ni = 0; ni < 6; ni++) \
                mma16(acc[mi][ni], af[mi], &bp[ni >> 1][(ni & 1) * 2]); \
    }

#define CLEAR_ACC() \
    _Pragma("unroll") \
    for (int mi = 0; mi < 2; mi++) \
        _Pragma("unroll") \
        for (int ni = 0; ni < 6; ni++) \
            _Pragma("unroll") \
            for (int c = 0; c < 4; c++) acc[mi][ni][c] = 0.f;

// B chunk loader (192 rows): lm = tid>>3 (0..63), 3 iterations of 64 rows
#define ISSUE_B(buf, nt, c) do { \
        const uint32_t bd = bBase + (uint32_t)(buf) * BCHUNK + (uint32_t)lm * 128 + bswz; \
        const __half* sb = B + ((long)(nt) * 192 + lm) * Cdim + (c) * 64 + lq * 8; \
        _Pragma("unroll") \
        for (int it = 0; it < 3; it++) \
            cp_async16(bd + it * 8192, sb + (long)it * 64 * Cdim); \
        asm volatile("cp.async.commit_group;" ::: "memory"); \
    } while (0)

// ---------------------------------------------------------------------------
// Fused LN + GEMM (QKV): C[M,N] = LN(gather(A))[M,192] @ B[N,192]^T + bias
// ---------------------------------------------------------------------------
#define LN_SMEM (3*ACHUNK + 2*BCHUNK + 128)

__global__ void __launch_bounds__(NTHREADS, 1)
gemm_ln(const float* __restrict__ Asrc, const __half* __restrict__ B,
        const float* __restrict__ bias, const float* __restrict__ gamma,
        const float* __restrict__ beta, __half* __restrict__ C, int N)
{
    extern __shared__ char dsm[];
    const uint32_t base  = (smem_u32(dsm) + 127u) & ~127u;
    const uint32_t bBase = base + 3 * ACHUNK;

    DECOMP();
    LDSM_SETUP();
    const long m0 = (long)blockIdx.x * 128;
    const int lm = tid >> 3;
    const int lq = tid & 7;
    const uint32_t bswz = (uint32_t)((lq ^ (lm & 7)) << 4);
    const int NT = N / 192;

    ISSUE_B(0, 0, 0);

    // Phase 1: LN of gathered A (each warp: 8 rows)
#pragma unroll 1
    for (int rr = 0; rr < 8; rr++) {
        const int row = wid * 8 + rr;
        const long t = m0 + row;
        const float* src = Asrc + win2orig(t) * Cdim;
        float2 v[3];
        float s = 0.f, ss = 0.f;
#pragma unroll
        for (int i = 0; i < 3; i++) {
            v[i] = *(const float2*)(src + 2 * lane + 64 * i);
            s  += v[i].x + v[i].y;
            ss += v[i].x * v[i].x + v[i].y * v[i].y;
        }
#pragma unroll
        for (int o = 16; o > 0; o >>= 1) {
            s  += __shfl_xor_sync(0xffffffffu, s,  o);
            ss += __shfl_xor_sync(0xffffffffu, ss, o);
        }
        const float mu  = s * (1.f / Cdim);
        const float var = ss * (1.f / Cdim) - mu * mu;
        const float r   = rsqrtf(var + 1e-5f);
        const uint32_t rowaddr = base + (uint32_t)row * 128 +
            ((((uint32_t)lane >> 2) ^ ((uint32_t)row & 7)) << 4) + ((uint32_t)lane & 3) * 4;
#pragma unroll
        for (int i = 0; i < 3; i++) {
            const int c = 2 * lane + 64 * i;
            const float2 gm = *(const float2*)(gamma + c);
            const float2 bt = *(const float2*)(beta + c);
            const __half2 hv = __floats2half2_rn((v[i].x - mu) * r * gm.x + bt.x,
                                                 (v[i].y - mu) * r * gm.y + bt.y);
            sts32(rowaddr + (uint32_t)i * ACHUNK, *(const uint32_t*)&hv);
        }
    }

    float acc[2][6][4];
    CLEAR_ACC();

    const int total = NT * 3;
    for (int ci = 0; ci < total; ci++) {
        const int c = ci % 3;
        if (ci + 1 < total) {
            const int cn = ci + 1;
            ISSUE_B(cn & 1, cn / 3, cn % 3);
            asm volatile("cp.async.wait_group 1;" ::: "memory");
        } else {
            asm volatile("cp.async.wait_group 0;" ::: "memory");
        }
        __syncthreads();

        KCHUNK_MMA(base + (uint32_t)c * ACHUNK, bBase + (uint32_t)(ci & 1) * BCHUNK);

        if (c == 2) {
            const int nt = ci / 3;
#pragma unroll
            for (int mi = 0; mi < 2; mi++) {
                const long r0 = m0 + m0w + mi * 16 + g;
                const long r1 = r0 + 8;
#pragma unroll
                for (int ni = 0; ni < 6; ni++) {
                    const int col = nt * 192 + n0w + ni * 8 + 2 * tig;
                    const float b0 = bias[col], b1 = bias[col + 1];
                    *(__half2*)(C + r0 * N + col) =
                        __floats2half2_rn(acc[mi][ni][0] + b0, acc[mi][ni][1] + b1);
                    *(__half2*)(C + r1 * N + col) =
                        __floats2half2_rn(acc[mi][ni][2] + b0, acc[mi][ni][3] + b1);
                    acc[mi][ni][0] = 0.f; acc[mi][ni][1] = 0.f;
                    acc[mi][ni][2] = 0.f; acc[mi][ni][3] = 0.f;
                }
            }
        }
        __syncthreads();
    }
}

// ---------------------------------------------------------------------------
// A-resident fp16 GEMM (FC1): C = GELU(A[M,192] @ B[N,192]^T + bias), half out
// ---------------------------------------------------------------------------
#define HA_SMEM (3*ACHUNK + 2*BCHUNK + 128)

__global__ void __launch_bounds__(NTHREADS, 1)
gemm_ha(const __half* __restrict__ A, const __half* __restrict__ B,
        const float* __restrict__ bias, __half* __restrict__ C, int N)
{
    extern __shared__ char dsm[];
    const uint32_t base  = (smem_u32(dsm) + 127u) & ~127u;
    const uint32_t bBase = base + 3 * ACHUNK;

    DECOMP();
    LDSM_SETUP();
    const long m0 = (long)blockIdx.x * 128;
    const int lm = tid >> 3;
    const int lq = tid & 7;
    const uint32_t bswz = (uint32_t)((lq ^ (lm & 7)) << 4);
    const int NT = N / 192;

    // A resident: 128 rows x 3 chunks
    {
        const uint32_t da = base + (uint32_t)lm * 128 + bswz;
        const __half* sa = A + (m0 + lm) * Cdim + lq * 8;
#pragma unroll
        for (int c = 0; c < 3; c++)
#pragma unroll
            for (int it = 0; it < 2; it++)
                cp_async16(da + (uint32_t)c * ACHUNK + it * 8192,
                           sa + (long)it * 64 * Cdim + c * 64);
        asm volatile("cp.async.commit_group;" ::: "memory");
    }

    ISSUE_B(0, 0, 0);

    float acc[2][6][4];
    CLEAR_ACC();

    const int total = NT * 3;
    for (int ci = 0; ci < total; ci++) {
        const int c = ci % 3;
        if (ci + 1 < total) {
            const int cn = ci + 1;
            ISSUE_B(cn & 1, cn / 3, cn % 3);
            asm volatile("cp.async.wait_group 1;" ::: "memory");
        } else {
            asm volatile("cp.async.wait_group 0;" ::: "memory");
        }
        __syncthreads();

        KCHUNK_MMA(base + (uint32_t)c * ACHUNK, bBase + (uint32_t)(ci & 1) * BCHUNK);

        if (c == 2) {
            const int nt = ci / 3;
#pragma unroll
            for (int mi = 0; mi < 2; mi++) {
                const long r0 = m0 + m0w + mi * 16 + g;
                const long r1 = r0 + 8;
#pragma unroll
                for (int ni = 0; ni < 6; ni++) {
                    const int col = nt * 192 + n0w + ni * 8 + 2 * tig;
                    const float b0 = bias[col], b1 = bias[col + 1];
                    float v0 = acc[mi][ni][0] + b0;
                    float v1 = acc[mi][ni][1] + b1;
                    float v2 = acc[mi][ni][2] + b0;
                    float v3 = acc[mi][ni][3] + b1;
                    v0 = 0.5f * v0 * (1.f + erff(v0 * 0.7071067811865475f));
                    v1 = 0.5f * v1 * (1.f + erff(v1 * 0.7071067811865475f));
                    v2 = 0.5f * v2 * (1.f + erff(v2 * 0.7071067811865475f));
                    v3 = 0.5f * v3 * (1.f + erff(v3 * 0.7071067811865475f));
                    *(__half2*)(C + r0 * N + col) = __floats2half2_rn(v0, v1);
                    *(__half2*)(C + r1 * N + col) = __floats2half2_rn(v2, v3);
                    acc[mi][ni][0] = 0.f; acc[mi][ni][1] = 0.f;
                    acc[mi][ni][2] = 0.f; acc[mi][ni][3] = 0.f;
                }
            }
        }
        __syncthreads();
    }
}

// ---------------------------------------------------------------------------
// Streaming fp16 GEMM.
// EPI=2: FC2 (+res fp32 -> out fp32)
// EPI=3: proj (unshift + x residual -> x1 fp32, LN2 -> ln2 half)
// ---------------------------------------------------------------------------
#define ASTAGE 16384
#define BSTAGE 24576
#define STAGE  (ASTAGE + BSTAGE)
#define GEMM_SMEM (2*STAGE + 128)

template <int EPI>
__global__ void __launch_bounds__(NTHREADS, 1)
gemm_h(const __half* __restrict__ A, const __half* __restrict__ Bw,
       const float* __restrict__ bias, const float* __restrict__ res,
       float* __restrict__ C, __half* __restrict__ C2,
       const float* __restrict__ gamma, const float* __restrict__ beta,
       int N, int K)
{
    extern __shared__ char dsm[];
    const uint32_t base = (smem_u32(dsm) + 127u) & ~127u;

    DECOMP();
    LDSM_SETUP();
    const long m0 = (long)blockIdx.x * 128;
    const int  n0 = blockIdx.y * 192;

    const int lm = tid >> 3;
    const int lq = tid & 7;
    const __half* srcA = A + (m0 + lm) * K + lq * 8;
    const __half* srcB = Bw + (long)(n0 + lm) * K + lq * 8;
    const uint32_t swz = (uint32_t)((lq ^ (lm & 7)) << 4);
    const uint32_t dstA0 = base + (uint32_t)lm * 128 + swz;
    const uint32_t dstB0 = base + ASTAGE + (uint32_t)lm * 128 + swz;

    float acc[2][6][4];
    CLEAR_ACC();

    const int NC = K >> 6;

#define ISSUE(buf, kc_) do { \
        const uint32_t so = (uint32_t)(buf) * STAGE; \
        const __half* sa = srcA + (kc_); \
        const __half* sb = srcB + (kc_); \
        _Pragma("unroll") \
        for (int it = 0; it < 2; it++) \
            cp_async16(dstA0 + so + it * 8192, sa + (long)it * 64 * K); \
        _Pragma("unroll") \
        for (int it = 0; it < 3; it++) \
            cp_async16(dstB0 + so + it * 8192, sb + (long)it * 64 * K); \
        asm volatile("cp.async.commit_group;" ::: "memory"); \
    } while (0)

    ISSUE(0, 0);

    for (int i = 0; i < NC; i++) {
        if (i + 1 < NC) {
            ISSUE((i + 1) & 1, (i + 1) << 6);
            asm volatile("cp.async.wait_group 1;" ::: "memory");
        } else {
            asm volatile("cp.async.wait_group 0;" ::: "memory");
        }
        __syncthreads();

        const uint32_t so = (uint32_t)(i & 1) * STAGE;
        KCHUNK_MMA(base + so, base + ASTAGE + so);
        __syncthreads();
    }
#undef ISSUE

    // bias + residual into acc
#pragma unroll
    for (int mi = 0; mi < 2; mi++) {
        const long rw0 = m0 + m0w + mi * 16 + g;
        const long rw1 = rw0 + 8;
        const long r0 = (EPI == 3) ? win2orig(rw0) : rw0;
        const long r1 = (EPI == 3) ? win2orig(rw1) : rw1;
#pragma unroll
        for (int ni = 0; ni < 6; ni++) {
            const int col = n0 + n0w + ni * 8 + 2 * tig;
            const float b0 = bias[col], b1 = bias[col + 1];
            const float2 ra = *(const float2*)(res + r0 * N + col);
            const float2 rb = *(const float2*)(res + r1 * N + col);
            acc[mi][ni][0] += b0 + ra.x;
            acc[mi][ni][1] += b1 + ra.y;
            acc[mi][ni][2] += b0 + rb.x;
            acc[mi][ni][3] += b1 + rb.y;
        }
    }

    if (EPI == 3) {
        float* rsum   = (float*)(dsm);
        float* rsumsq = rsum + 128;
        if (tid < 128) { rsum[tid] = 0.f; rsumsq[tid] = 0.f; }
        __syncthreads();
#pragma unroll
        for (int mi = 0; mi < 2; mi++) {
            const int row0 = m0w + mi * 16 + g;
            float s0 = 0.f, q0 = 0.f, s1 = 0.f, q1 = 0.f;
#pragma unroll
            for (int ni = 0; ni < 6; ni++) {
                s0 += acc[mi][ni][0] + acc[mi][ni][1];
                q0 += acc[mi][ni][0] * acc[mi][ni][0] + acc[mi][ni][1] * acc[mi][ni][1];
                s1 += acc[mi][ni][2] + acc[mi][ni][3];
                q1 += acc[mi][ni][2] * acc[mi][ni][2] + acc[mi][ni][3] * acc[mi][ni][3];
            }
            atomicAdd(&rsum[row0], s0);     atomicAdd(&rsumsq[row0], q0);
            atomicAdd(&rsum[row0 + 8], s1); atomicAdd(&rsumsq[row0 + 8], q1);
        }
        __syncthreads();
    }

#pragma unroll
    for (int mi = 0; mi < 2; mi++) {
        const long rw0 = m0 + m0w + mi * 16 + g;
        const long rw1 = rw0 + 8;
        const long r0 = (EPI == 3) ? win2orig(rw0) : rw0;
        const long r1 = (EPI == 3) ? win2orig(rw1) : rw1;

        float mu0 = 0.f, rs0 = 0.f, mu1 = 0.f, rs1 = 0.f;
        if (EPI == 3) {
            const float* rsum   = (const float*)(dsm);
            const float* rsumsq = rsum + 128;
            const int row0 = m0w + mi * 16 + g;
            mu0 = rsum[row0] * (1.f / Cdim);
            rs0 = rsqrtf(rsumsq[row0] * (1.f / Cdim) - mu0 * mu0 + 1e-5f);
            mu1 = rsum[row0 + 8] * (1.f / Cdim);
            rs1 = rsqrtf(rsumsq[row0 + 8] * (1.f / Cdim) - mu1 * mu1 + 1e-5f);
        }
#pragma unroll
        for (int ni = 0; ni < 6; ni++) {
            const int col = n0 + n0w + ni * 8 + 2 * tig;
            const float v0 = acc[mi][ni][0], v1 = acc[mi][ni][1];
            const float v2 = acc[mi][ni][2], v3 = acc[mi][ni][3];
            *(float2*)(C + r0 * N + col) = make_float2(v0, v1);
            *(float2*)(C + r1 * N + col) = make_float2(v2, v3);
            if (EPI == 3) {
                const float2 gm = *(const float2*)(gamma + col);
                const float2 bt = *(const float2*)(beta + col);
                *(__half2*)(C2 + r0 * N + col) = __floats2half2_rn(
                    (v0 - mu0) * rs0 * gm.x + bt.x, (v1 - mu0) * rs0 * gm.y + bt.y);
                *(__half2*)(C2 + r1 * N + col) = __floats2half2_rn(
                    (v2 - mu1) * rs1 * gm.x + bt.x, (v3 - mu1) * rs1 * gm.y + bt.y);
            }
        }
    }
}

// ---------------------------------------------------------------------------
// One-shot weight conversion fp32 -> fp16 (4 tensors)
// ---------------------------------------------------------------------------
__global__ void tohalf_all(const float* __restrict__ s0, const float* __restrict__ s1,
                           const float* __restrict__ s2, const float* __restrict__ s3,
                           __half* __restrict__ dst)
{
    const int i = blockIdx.x * 1024 + threadIdx.x * 4;
    const float* src;
    int off;
    if (i < 110592)      { src = s0; off = 0; }
    else if (i < 147456) { src = s1; off = 110592; }
    else if (i < 294912) { src = s2; off = 147456; }
    else                 { src = s3; off = 294912; }
    const float4 v = *(const float4*)(src + (i - off));
    __half2* d = (__half2*)(dst + i);
    d[0] = __floats2half2_rn(v.x, v.y);
    d[1] = __floats2half2_rn(v.z, v.w);
}

// ---------------------------------------------------------------------------
// Fused window attention. Block per (window, head), 64 threads.
// ---------------------------------------------------------------------------
__global__ void __launch_bounds__(64)
attn_kernel(const __half* __restrict__ qkv,
            const float* __restrict__ rpb,
            __half* __restrict__ out)
{
    const int win  = blockIdx.x;
    const int head = blockIdx.y;
    const int n    = threadIdx.x;

    __shared__ float ks[64][36];
    __shared__ float vs[64][36];
    __shared__ float sp[64][65];
    __shared__ float sbias[225];
    __shared__ int   lab[64];

    const __half* base = qkv + (long)win * NPW * (3 * Cdim);
    const __half2* k2 = (const __half2*)(base + n * (3 * Cdim) + Cdim + head * HD);
    const __half2* v2 = (const __half2*)(base + n * (3 * Cdim) + 2 * Cdim + head * HD);
#pragma unroll
    for (int dp = 0; dp < 16; dp++) {
        const float2 fk = __half22float2(k2[dp]);
        const float2 fv = __half22float2(v2[dp]);
        ks[n][2 * dp] = fk.x; ks[n][2 * dp + 1] = fk.y;
        vs[n][2 * dp] = fv.x; vs[n][2 * dp + 1] = fv.y;
    }
    for (int idx = n; idx < 225; idx += 64) sbias[idx] = rpb[idx * NH + head];
    {
        const int wi = win & 255;
        const int gh = (wi >> 4) * 8 + (n >> 3);
        const int gw = (wi & 15) * 8 + (n & 7);
        const int rh = (gh < Himg - WS) ? 0 : ((gh < Himg - SHIFT) ? 1 : 2);
        const int rw = (gw < Wimg - WS) ? 0 : ((gw < Wimg - SHIFT) ? 1 : 2);
        lab[n] = rh * 3 + rw;
    }
    __syncthreads();

    float q[HD];
    const __half2* q2 = (const __half2*)(base + n * (3 * Cdim) + head * HD);
#pragma unroll
    for (int dp = 0; dp < 16; dp++) {
        const float2 f = __half22float2(q2[dp]);
        q[2 * dp]     = f.x * 0.17677669529663687f;
        q[2 * dp + 1] = f.y * 0.17677669529663687f;
    }

    const int i = n >> 3, j = n & 7;
    const int myl = lab[n];

    float mx = -1e30f;
    for (int m = 0; m < 64; m++) {
        const float4* kr = (const float4*)&ks[m][0];
        float s = 0.f;
#pragma unroll
        for (int t = 0; t < 8; t++) {
            const float4 kv = kr[t];
            s += q[4*t] * kv.x + q[4*t+1] * kv.y + q[4*t+2] * kv.z + q[4*t+3] * kv.w;
        }
        s += sbias[(i - (m >> 3) + 7) * 15 + (j - (m & 7) + 7)];
        if (lab[m] != myl) s -= 100.f;
        sp[n][m] = s;
        mx = fmaxf(mx, s);
    }
    float sum = 0.f;
    for (int m = 0; m < 64; m++) {
        const float e = expf(sp[n][m] - mx);
        sp[n][m] = e; sum += e;
    }
    const float inv = 1.f / sum;

    float accv[HD];
#pragma unroll
    for (int d = 0; d < HD; d++) accv[d] = 0.f;
    for (int m = 0; m < 64; m++) {
        const float p = sp[n][m];
        const float4* vr = (const float4*)&vs[m][0];
#pragma unroll
        for (int t = 0; t < 8; t++) {
            const float4 vv = vr[t];
            accv[4*t]   += p * vv.x;
            accv[4*t+1] += p * vv.y;
            accv[4*t+2] += p * vv.z;
            accv[4*t+3] += p * vv.w;
        }
    }
    __half* dst = out + ((long)win * NPW + n) * Cdim + head * HD;
#pragma unroll
    for (int dp = 0; dp < 16; dp++)
        *(__half2*)(dst + 2 * dp) = __floats2half2_rn(accv[2*dp] * inv, accv[2*dp+1] * inv);
}

// ---------------------------------------------------------------------------
// Launch
// ---------------------------------------------------------------------------
extern "C" void kernel_launch(void* const* d_in, const int* in_sizes, int n_in,
                              void* d_out, int out_size)
{
    const float* x      = (const float*)d_in[0];
    const float* g1     = (const float*)d_in[1];
    const float* b1     = (const float*)d_in[2];
    const float* qkv_w  = (const float*)d_in[3];
    const float* qkv_b  = (const float*)d_in[4];
    const float* rpb    = (const float*)d_in[5];
    const float* proj_w = (const float*)d_in[6];
    const float* proj_b = (const float*)d_in[7];
    const float* g2     = (const float*)d_in[8];
    const float* b2     = (const float*)d_in[9];
    const float* fc1_w  = (const float*)d_in[10];
    const float* fc1_b  = (const float*)d_in[11];
    const float* fc2_w  = (const float*)d_in[12];
    const float* fc2_b  = (const float*)d_in[13];
    float* out = (float*)d_out;

    __half *p_qkv, *p_att, *p_ln2, *p_hh, *p_wh;
    float *p_x1;
    cudaGetSymbolAddress((void**)&p_qkv, g_qkv);
    cudaGetSymbolAddress((void**)&p_att, g_att);
    cudaGetSymbolAddress((void**)&p_ln2, g_ln2);
    cudaGetSymbolAddress((void**)&p_hh,  g_hh);
    cudaGetSymbolAddress((void**)&p_x1,  g_x1);
    cudaGetSymbolAddress((void**)&p_wh,  g_wh);

    static bool attr_set = false;
    if (!attr_set) {
        cudaFuncSetAttribute(gemm_ln, cudaFuncAttributeMaxDynamicSharedMemorySize, LN_SMEM);
        cudaFuncSetAttribute(gemm_ha, cudaFuncAttributeMaxDynamicSharedMemorySize, HA_SMEM);
        cudaFuncSetAttribute(gemm_h<3>, cudaFuncAttributeMaxDynamicSharedMemorySize, GEMM_SMEM);
        cudaFuncSetAttribute(gemm_h<2>, cudaFuncAttributeMaxDynamicSharedMemorySize, GEMM_SMEM);
        attr_set = true;
    }

    __half* w_qkv = p_wh;
    __half* w_prj = p_wh + 110592;
    __half* w_fc1 = p_wh + 147456;
    __half* w_fc2 = p_wh + 294912;

    // 0. weights fp32 -> fp16
    tohalf_all<<<442368 / 1024, 256>>>(qkv_w, proj_w, fc1_w, fc2_w, p_wh);

    const int M = NTOK;  // 131072, 1024 M-tiles

    // 1. QKV (fused LN1 + shift/window gather)
    gemm_ln<<<M / 128, NTHREADS, LN_SMEM>>>(x, w_qkv, qkv_b, g1, b1, p_qkv, 3 * Cdim);

    // 2. Window attention
    attn_kernel<<<dim3(NWIN, NH), 64>>>(p_qkv, rpb, p_att);

    // 3. proj + unshift + x residual -> x1 fp32; fused LN2 -> ln2 half
    gemm_h<3><<<dim3(M / 128, 1), NTHREADS, GEMM_SMEM>>>(
        p_att, w_prj, proj_b, x, p_x1, p_ln2, g2, b2, Cdim, Cdim);

    // 4. FC1 + GELU (A-resident)
    gemm_ha<<<M / 128, NTHREADS, HA_SMEM>>>(p_ln2, w_fc1, fc1_b, p_hh, HID);

    // 5. FC2 + x1 residual -> out fp32
    gemm_h<2><<<dim3(M / 128, 1), NTHREADS, GEMM_SMEM>>>(
        p_hh, w_fc2, fc2_b, p_x1, out, nullptr, nullptr, nullptr, Cdim, HID);
}